// round 11
// baseline (speedup 1.0000x reference)
#include <cuda_runtime.h>
#include <cstdint>
#include <math.h>

typedef unsigned long long ULL;

// ---------------- scratch offsets (floats) ----------------
#define OFF_WORDS 0ull                               // 4096*128
#define OFF_XG0F (OFF_WORDS + 524288ull)             // 4096*500
#define OFF_XG0B (OFF_XG0F + 2048000ull)
#define OFF_XG1F (OFF_XG0B + 2048000ull)
#define OFF_XG1B (OFF_XG1F + 2048000ull)
#define OFF_H0   (OFF_XG1B + 2048000ull)             // 4096*256
#define OFF_WE1  (OFF_H0   + 1048576ull)             // 4096*256
#define OFF_SCOR (OFF_WE1  + 1048576ull)             // 4096*400
#define OFF_WIH0 (OFF_SCOR + 1638400ull)             // 2*512*128
#define OFF_WIH1 (OFF_WIH0 + 131072ull)              // 2*512*256
#define OFF_SW   (OFF_WIH1 + 262144ull)              // 448*256
#define OFF_B0   (OFF_SW   + 114688ull)              // 2*512
#define OFF_B1   (OFF_B0   + 1024ull)                // 2*512
#define OFF_SB   (OFF_B1   + 1024ull)                // 448
#define SCR_TOT  (OFF_SB   + 448ull)

__device__ float g_scr[SCR_TOT];
__device__ int   g_tree[4096];
__device__ int   g_gidx[4096];
__device__ ULL   g_wpk[4 * 63 * 512];   // packed Whh pair image [ld][63][512]

// ---------------- f32x2 helpers ----------------
__device__ __forceinline__ ULL pk2(float x, float y) {
    ULL r; asm("mov.b64 %0,{%1,%2};" : "=l"(r) : "f"(x), "f"(y)); return r;
}
__device__ __forceinline__ float2 upk2(ULL v) {
    float2 r; asm("mov.b64 {%0,%1},%2;" : "=f"(r.x), "=f"(r.y) : "l"(v)); return r;
}
__device__ __forceinline__ void fma2(ULL& c, ULL a, ULL b) {
    asm("fma.rn.f32x2 %0,%1,%2,%0;" : "+l"(c) : "l"(a), "l"(b));
}
__device__ __forceinline__ float sig_f(float x) {
    x = fminf(15.f, fmaxf(-15.f, x));
    float e; asm("ex2.approx.f32 %0,%1;" : "=f"(e) : "f"(-1.4426950408889634f * x));
    float r; asm("rcp.approx.f32 %0,%1;" : "=f"(r) : "f"(1.f + e));
    return r;
}
__device__ __forceinline__ float tanh_f(float x) {
    x = fminf(15.f, fmaxf(-15.f, x));
    float e; asm("ex2.approx.f32 %0,%1;" : "=f"(e) : "f"(2.885390081777927f * x));
    float r; asm("rcp.approx.f32 %0,%1;" : "=f"(r) : "f"(e + 1.f));
    return (e - 1.f) * r;
}
__device__ __forceinline__ uint32_t sa(const void* p) {
    return (uint32_t)__cvta_generic_to_shared(p);
}

// ---------------- prep: pack/pad weights, biases, tree/gidx, Whh image ----------------
__global__ void k_prep(const int* __restrict__ tarc,
                       const float* __restrict__ l0fW, const float* __restrict__ l0bW,
                       const float* __restrict__ l1fW, const float* __restrict__ l1bW,
                       const float* __restrict__ ehW, const float* __restrict__ emW,
                       const float* __restrict__ lmW, const float* __restrict__ lhW,
                       const float* __restrict__ l0fb, const float* __restrict__ l0bb,
                       const float* __restrict__ l1fb, const float* __restrict__ l1bb,
                       const float* __restrict__ ehb, const float* __restrict__ emb,
                       const float* __restrict__ lmb, const float* __restrict__ lhb,
                       const float* __restrict__ whl0f, const float* __restrict__ whl0b,
                       const float* __restrict__ whl1f, const float* __restrict__ whl1b) {
    int idx = blockIdx.x * 256 + threadIdx.x;
    const int E0 = 131072, E1 = E0 + 262144, E2 = E1 + 114688, E3 = E2 + 1024,
              E4 = E3 + 1024, E5 = E4 + 448, E6 = E5 + 4096, E7 = E6 + 24576,
              E8 = E7 + 24576, E9 = E8 + 129024;
    if (idx < E0) {                       // WIH0 [2][512][128]
        int z = idx >> 16, r = idx & 65535, n = r >> 7, k = r & 127;
        const float* s = z ? l0bW : l0fW;
        g_scr[OFF_WIH0 + idx] = (n < 500 && k < 125) ? s[n * 125 + k] : 0.f;
    } else if (idx < E1) {                // WIH1 [2][512][256]
        int i = idx - E0, z = i >> 17, r = i & 131071, n = r >> 8, k = r & 255;
        const float* s = z ? l1bW : l1fW;
        g_scr[OFF_WIH1 + i] = (n < 500 && k < 250) ? s[n * 250 + k] : 0.f;
    } else if (idx < E2) {                // SW [448][256]
        int i = idx - E1, n = i >> 8, k = i & 255;
        float v = 0.f;
        if (k < 250 && n < 400) {
            int sel = n / 100, nn = n - sel * 100;
            const float* s = sel == 0 ? ehW : sel == 1 ? emW : sel == 2 ? lmW : lhW;
            v = s[nn * 250 + k];
        }
        g_scr[OFF_SW + i] = v;
    } else if (idx < E3) {                // B0 [2][512]
        int i = idx - E2, z = i >> 9, n = i & 511;
        g_scr[OFF_B0 + i] = (n < 500) ? (z ? l0bb[n] : l0fb[n]) : 0.f;
    } else if (idx < E4) {                // B1 [2][512]
        int i = idx - E3, z = i >> 9, n = i & 511;
        g_scr[OFF_B1 + i] = (n < 500) ? (z ? l1bb[n] : l1fb[n]) : 0.f;
    } else if (idx < E5) {                // SB [448]
        int n = idx - E4;
        float v = 0.f;
        if (n < 400) {
            int sel = n / 100, nn = n - sel * 100;
            v = sel == 0 ? ehb[nn] : sel == 1 ? emb[nn] : sel == 2 ? lmb[nn] : lhb[nn];
        }
        g_scr[OFF_SB + n] = v;
    } else if (idx < E6) {                // tree + gidx
        int m = idx - E5;
        int v = ((m & 127) == 0) ? 0 : tarc[m];
        g_tree[m] = v;
        g_gidx[m] = (m >> 7) * 128 + v;
    } else if (idx < E7) {                // H0 pad cols 250..255
        int i = idx - E6, m = i / 6, c = i - m * 6;
        g_scr[OFF_H0 + (size_t)m * 256 + 250 + c] = 0.f;
    } else if (idx < E8) {                // WE1 pad cols
        int i = idx - E7, m = i / 6, c = i - m * 6;
        g_scr[OFF_WE1 + (size_t)m * 256 + 250 + c] = 0.f;
    } else if (idx < E9) {                // g_wpk [4][63][512]
        int i = idx - E8;
        int ld = i / 32256, rem = i - ld * 32256;
        int k = rem >> 9, r = rem & 511;
        const float* s = ld == 0 ? whl0f : ld == 1 ? whl0b : ld == 2 ? whl1f : whl1b;
        float w0 = 0.f, w1 = 0.f;
        if (r < 500) {
            int c0 = 2 * k, c1 = 2 * k + 1;
            if (c0 < 125) w0 = s[r * 125 + c0];
            if (c1 < 125) w1 = s[r * 125 + c1];
        }
        g_wpk[i] = pk2(w0, w1);
    }
}

// ---------------- embedding gather: words[4096,128] (padded) ----------------
__global__ void k_embed(const int* __restrict__ wid, const int* __restrict__ uid,
                        const float* __restrict__ wl, const float* __restrict__ tl) {
    int m = blockIdx.x, t = threadIdx.x;
    float* w = g_scr + OFF_WORDS + (size_t)m * 128;
    float v = 0.f;
    if (t < 100)      v = wl[(size_t)wid[m] * 100 + t];
    else if (t < 125) v = tl[(size_t)uid[m] * 25 + (t - 100)];
    w[t] = v;
}

// ---------------- GEMM: C[z][4096,N] = A[4096,K] @ Wp[z][Npad,K]^T + Bp[z] ----------------
// AsDup rows padded to 66 ULLs (528B stride, 16B-aligned for ld.shared.v2.u64).
__global__ void __launch_bounds__(256) k_gemm(const float* __restrict__ A,
                                              const float* __restrict__ Wp,
                                              const float* __restrict__ Bp,
                                              float* __restrict__ C,
                                              int N, int K, int ldWz, int bstride,
                                              long long zsC) {
    __shared__ __align__(16) ULL  AsDup[32][66];
    __shared__ __align__(16) float Ws[32][68];
    int z = blockIdx.z;
    const float* Wz = Wp + (size_t)z * ldWz;
    const float* bz = Bp + (size_t)z * bstride;
    float* Cz = C + (size_t)z * zsC;
    int t = threadIdx.x, tx = t & 15, ty = t >> 4;
    int m0 = blockIdx.y * 64, n0 = blockIdx.x * 64;
    int mf = t >> 3, kg = t & 7;

    ULL acc[4][2];
#pragma unroll
    for (int i = 0; i < 4; i++) { acc[i][0] = 0ull; acc[i][1] = 0ull; }

    uint32_t aAddr = sa(&AsDup[0][ty * 4]);
    uint32_t wAddr = sa(&Ws[0][tx * 4]);

    for (int k0 = 0; k0 < K; k0 += 32) {
        float4 av1 = *(const float4*)(A  + (size_t)(m0 + mf) * K + k0 + kg * 4);
        float4 av2 = *(const float4*)(A  + (size_t)(m0 + mf + 32) * K + k0 + kg * 4);
        float4 wv1 = *(const float4*)(Wz + (size_t)(n0 + mf) * K + k0 + kg * 4);
        float4 wv2 = *(const float4*)(Wz + (size_t)(n0 + mf + 32) * K + k0 + kg * 4);
        AsDup[kg * 4 + 0][mf] = pk2(av1.x, av1.x);
        AsDup[kg * 4 + 1][mf] = pk2(av1.y, av1.y);
        AsDup[kg * 4 + 2][mf] = pk2(av1.z, av1.z);
        AsDup[kg * 4 + 3][mf] = pk2(av1.w, av1.w);
        AsDup[kg * 4 + 0][mf + 32] = pk2(av2.x, av2.x);
        AsDup[kg * 4 + 1][mf + 32] = pk2(av2.y, av2.y);
        AsDup[kg * 4 + 2][mf + 32] = pk2(av2.z, av2.z);
        AsDup[kg * 4 + 3][mf + 32] = pk2(av2.w, av2.w);
        Ws[kg * 4 + 0][mf] = wv1.x; Ws[kg * 4 + 1][mf] = wv1.y;
        Ws[kg * 4 + 2][mf] = wv1.z; Ws[kg * 4 + 3][mf] = wv1.w;
        Ws[kg * 4 + 0][mf + 32] = wv2.x; Ws[kg * 4 + 1][mf + 32] = wv2.y;
        Ws[kg * 4 + 2][mf + 32] = wv2.z; Ws[kg * 4 + 3][mf + 32] = wv2.w;
        __syncthreads();
#pragma unroll
        for (int k = 0; k < 32; k++) {
            ULL a0, a1, a2, a3, w01, w23;
            asm volatile("ld.shared.v2.u64 {%0,%1},[%2];"
                         : "=l"(a0), "=l"(a1) : "r"(aAddr + k * 528));
            asm volatile("ld.shared.v2.u64 {%0,%1},[%2];"
                         : "=l"(a2), "=l"(a3) : "r"(aAddr + k * 528 + 16));
            asm volatile("ld.shared.v2.u64 {%0,%1},[%2];"
                         : "=l"(w01), "=l"(w23) : "r"(wAddr + k * 272));
            fma2(acc[0][0], a0, w01); fma2(acc[0][1], a0, w23);
            fma2(acc[1][0], a1, w01); fma2(acc[1][1], a1, w23);
            fma2(acc[2][0], a2, w01); fma2(acc[2][1], a2, w23);
            fma2(acc[3][0], a3, w01); fma2(acc[3][1], a3, w23);
        }
        __syncthreads();
    }
    int n = n0 + tx * 4;
    float b0 = (n     < N) ? bz[n]     : 0.f;
    float b1 = (n + 1 < N) ? bz[n + 1] : 0.f;
    float b2 = (n + 2 < N) ? bz[n + 2] : 0.f;
    float b3 = (n + 3 < N) ? bz[n + 3] : 0.f;
#pragma unroll
    for (int i = 0; i < 4; i++) {
        int m = m0 + ty * 4 + i;
        float2 p0 = upk2(acc[i][0]), p1 = upk2(acc[i][1]);
        float4 v = make_float4(p0.x + b0, p0.y + b1, p1.x + b2, p1.y + b3);
        if (n + 3 < N) {
            *(float4*)(Cz + (size_t)m * N + n) = v;
        } else {
            float vv[4] = {v.x, v.y, v.z, v.w};
            for (int jj = 0; jj < 4; jj++)
                if (n + jj < N) Cz[(size_t)m * N + n + jj] = vv[jj];
        }
    }
}

// ---------------- LSTM scan: ONE CTA per (b,dir) ----------------
// Weights from pre-packed coalesced image: cols 0..87 in regs (44 f32x2),
// cols 88..125 streamed from smem (19 pair rows). Distributed activations,
// two-step xv prefetch.
#define SPAIR 19
#define SCAN_SMEM (SPAIR * 512 * 8 + 128 * 4 + 512 * 4)
__global__ void __launch_bounds__(512, 1)
k_scan(const float* __restrict__ xgf, const float* __restrict__ xgb,
       const ULL* __restrict__ wpkF, const ULL* __restrict__ wpkB,
       float* __restrict__ hout) {
    extern __shared__ __align__(16) char dyn[];
    ULL*   wsp  = (ULL*)dyn;                          // [SPAIR][512]
    float* h    = (float*)(dyn + SPAIR * 512 * 8);    // [128]
    float* gacc = h + 128;                            // [512]
    int bid = blockIdx.x;
    int b = bid & 31, dir = bid >> 5;
    const float* xg = dir ? xgb : xgf;
    const ULL* wpk  = dir ? wpkB : wpkF;
    int t = threadIdx.x;
    bool act = t < 500;
    int r = act ? t : 0;

    ULL wreg[44];
#pragma unroll
    for (int k = 0; k < 44; k++)
        wreg[k] = wpk[k * 512 + t];
#pragma unroll
    for (int k = 0; k < SPAIR; k++)
        wsp[k * 512 + t] = wpk[(44 + k) * 512 + t];
    if (t < 128) h[t] = 0.f;
    __syncthreads();

    uint32_t hA = sa(h);
    uint32_t wA = sa(wsp) + (uint32_t)t * 8;
    float c = 0.f;
    const size_t brow = (size_t)b * 128;
    float xvc = act ? xg[(brow + (dir ? 127 : 0)) * 500 + r] : 0.f;
    float xvn = act ? xg[(brow + (dir ? 126 : 1)) * 500 + r] : 0.f;
    bool istanh = (t >= 250 && t < 375);

    for (int s = 0; s < 128; s++) {
        int tt = dir ? (127 - s) : s;
        ULL a0 = 0ull, a1 = 0ull, a2 = 0ull, a3 = 0ull;
        // cols 0..87 from registers (22 x 4 cols)
#pragma unroll
        for (int i = 0; i < 22; i++) {
            ULL h01, h23;
            asm volatile("ld.shared.v2.u64 {%0,%1},[%2];"
                         : "=l"(h01), "=l"(h23) : "r"(hA + i * 16));
            if (i & 1) { fma2(a2, h01, wreg[2 * i]); fma2(a3, h23, wreg[2 * i + 1]); }
            else       { fma2(a0, h01, wreg[2 * i]); fma2(a1, h23, wreg[2 * i + 1]); }
        }
        // cols 88..123 from smem pairs 0..17
#pragma unroll
        for (int i = 0; i < 9; i++) {
            ULL h01, h23, w01, w23;
            asm volatile("ld.shared.v2.u64 {%0,%1},[%2];"
                         : "=l"(h01), "=l"(h23) : "r"(hA + 352 + i * 16));
            asm volatile("ld.shared.u64 %0,[%1];"
                         : "=l"(w01) : "r"(wA + (2 * i) * 4096));
            asm volatile("ld.shared.u64 %0,[%1];"
                         : "=l"(w23) : "r"(wA + (2 * i + 1) * 4096));
            if (i & 1) { fma2(a2, h01, w01); fma2(a3, h23, w23); }
            else       { fma2(a0, h01, w01); fma2(a1, h23, w23); }
        }
        // cols 124..125 (h[125..127]==0, weight col125 packed as 0)
        {
            ULL h01, w01;
            asm volatile("ld.shared.u64 %0,[%1];" : "=l"(h01) : "r"(hA + 496));
            asm volatile("ld.shared.u64 %0,[%1];" : "=l"(w01) : "r"(wA + 18 * 4096));
            fma2(a0, h01, w01);
        }
        float2 f0 = upk2(a0), f1 = upk2(a1), f2 = upk2(a2), f3 = upk2(a3);
        float g = ((f0.x + f0.y) + (f1.x + f1.y)) + ((f2.x + f2.y) + (f3.x + f3.y)) + xvc;
        // distributed activation: each thread activates its own gate row
        gacc[t] = istanh ? tanh_f(g) : sig_f(g);
        xvc = xvn;
        if (s + 2 < 128) {
            int tn = dir ? (125 - s) : (s + 2);
            xvn = act ? xg[(brow + tn) * 500 + r] : 0.f;
        }
        __syncthreads();
        if (t < 125) {
            float si = gacc[t], sf = gacc[125 + t], tg = gacc[250 + t], so = gacc[375 + t];
            c = sf * c + si * tg;
            float hh = so * tanh_f(c);
            h[t] = hh;
            hout[(brow + tt) * 256 + dir * 125 + t] = hh;
        }
        __syncthreads();
    }
}

// ---------------- biaffine arc scores + margin + argmax ----------------
__global__ void __launch_bounds__(256) k_arc(const float* __restrict__ esW,
                                             const float* __restrict__ esb,
                                             float* __restrict__ arc_out,
                                             float* __restrict__ parsed_out) {
    extern __shared__ float sm[];
    float* wms   = sm;                 // 128*101
    float* whs   = sm + 128 * 101;     // 16*101
    float* esw   = whs + 16 * 101;     // 100
    float* baseS = esw + 100;          // 1
    int*   treei = (int*)(baseS + 1);  // 16
    const float S = 2.885390081777927f; // 2*log2(e)
    int b = blockIdx.y, i0 = blockIdx.x * 16;
    int t = threadIdx.x;
    const float* wm = g_scr + OFF_SCOR + (size_t)b * 128 * 400 + 100;
    const float* wh = g_scr + OFF_SCOR + ((size_t)b * 128 + i0) * 400;
    for (int idx = t; idx < 12800; idx += 256) {
        int j = idx / 100, h = idx - j * 100;
        wms[j * 101 + h] = wm[(size_t)j * 400 + h] * S;
    }
    for (int idx = t; idx < 1600; idx += 256) {
        int ii = idx / 100, h = idx - ii * 100;
        whs[ii * 101 + h] = wh[(size_t)ii * 400 + h] * S;
    }
    if (t < 100) esw[t] = -2.f * esW[t];
    if (t == 0) {
        float ssum = 0.f;
        for (int h = 0; h < 100; h++) ssum += esW[h];
        baseS[0] = ssum + esb[0] + 1.f;
    }
    if (t < 16) treei[t] = g_tree[b * 128 + i0 + t];
    __syncthreads();

    int ii = t >> 4, jl = t & 15;
    int i = i0 + ii;
    int tgt = treei[ii];
    float base = baseS[0];
    float best = -1e30f; int bj = 0;
    float* arow = arc_out + ((size_t)b * 128 + i) * 128;
    const float* Arow = whs + ii * 101;
    for (int jt = 0; jt < 8; jt++) {
        int j = jl + 16 * jt;
        const float* Brow = wms + j * 101;
        float acc = 0.f;
#pragma unroll
        for (int h = 0; h < 100; h++) {
            float x = Arow[h] + Brow[h];
            float e; asm("ex2.approx.f32 %0, %1;" : "=f"(e) : "f"(x));
            float rr; asm("rcp.approx.f32 %0, %1;" : "=f"(rr) : "f"(1.f + e));
            acc = fmaf(esw[h], rr, acc);
        }
        float sc = base + acc - ((j == tgt) ? 1.f : 0.f);
        arow[j] = sc;
        if (sc > best) { best = sc; bj = j; }
    }
    for (int off = 8; off; off >>= 1) {
        float ob = __shfl_xor_sync(0xffffffffu, best, off);
        int   oj = __shfl_xor_sync(0xffffffffu, bj, off);
        if (ob > best || (ob == best && oj < bj)) { best = ob; bj = oj; }
    }
    if (jl == 0) parsed_out[b * 128 + i] = (float)bj;
}

// ---------------- rel scores + argmax (head gather post-projection) ----------------
__global__ void k_rel(const float* __restrict__ lsW, const float* __restrict__ lsb,
                      float* __restrict__ rel_out, float* __restrict__ pred_out) {
    __shared__ float th[100];
    __shared__ float sc[50];
    int m = blockIdx.x, t = threadIdx.x;
    const float* rm = g_scr + OFF_SCOR + (size_t)m * 400 + 200;
    const float* rh = g_scr + OFF_SCOR + (size_t)g_gidx[m] * 400 + 300;
    for (int h = t; h < 100; h += 64) th[h] = tanhf(rm[h] + rh[h]);
    __syncthreads();
    if (t < 50) {
        float acc = lsb[t];
        const float* wr = lsW + t * 100;
#pragma unroll 10
        for (int h = 0; h < 100; h++) acc = fmaf(th[h], wr[h], acc);
        rel_out[(size_t)m * 50 + t] = acc;
        sc[t] = acc;
    }
    __syncthreads();
    if (t == 0) {
        float best = sc[0]; int bl = 0;
        for (int l = 1; l < 50; l++) if (sc[l] > best) { best = sc[l]; bl = l; }
        pred_out[m] = (float)bl;
    }
}

// ---------------- launch ----------------
extern "C" void kernel_launch(void* const* d_in, const int* in_sizes, int n_in,
                              void* d_out, int out_size) {
    const int* wid  = (const int*)d_in[0];
    const int* uid  = (const int*)d_in[1];
    const int* tarc = (const int*)d_in[2];
    const float* wl = (const float*)d_in[3];
    const float* tl = (const float*)d_in[4];
    const float* l0f_Wih = (const float*)d_in[5];
    const float* l0f_Whh = (const float*)d_in[6];
    const float* l0f_b   = (const float*)d_in[7];
    const float* l0b_Wih = (const float*)d_in[8];
    const float* l0b_Whh = (const float*)d_in[9];
    const float* l0b_b   = (const float*)d_in[10];
    const float* l1f_Wih = (const float*)d_in[11];
    const float* l1f_Whh = (const float*)d_in[12];
    const float* l1f_b   = (const float*)d_in[13];
    const float* l1b_Wih = (const float*)d_in[14];
    const float* l1b_Whh = (const float*)d_in[15];
    const float* l1b_b   = (const float*)d_in[16];
    const float* ehW = (const float*)d_in[17];
    const float* ehb = (const float*)d_in[18];
    const float* emW = (const float*)d_in[19];
    const float* emb = (const float*)d_in[20];
    const float* esW = (const float*)d_in[21];
    const float* esb = (const float*)d_in[22];
    const float* lhW = (const float*)d_in[23];
    const float* lhb = (const float*)d_in[24];
    const float* lmW = (const float*)d_in[25];
    const float* lmb = (const float*)d_in[26];
    const float* lsW = (const float*)d_in[27];
    const float* lsb = (const float*)d_in[28];
    float* out = (float*)d_out;

    float* scr = nullptr;
    cudaGetSymbolAddress((void**)&scr, g_scr);
    ULL* wpk = nullptr;
    cudaGetSymbolAddress((void**)&wpk, g_wpk);
    float* WORDS = scr + OFF_WORDS;
    float* XG0F = scr + OFF_XG0F;
    float* XG0B = scr + OFF_XG0B;
    float* XG1F = scr + OFF_XG1F;
    float* XG1B = scr + OFF_XG1B;
    float* H0   = scr + OFF_H0;
    float* WE1  = scr + OFF_WE1;
    float* SCOR = scr + OFF_SCOR;
    float* WIH0 = scr + OFF_WIH0;
    float* WIH1 = scr + OFF_WIH1;
    float* SW   = scr + OFF_SW;
    float* B0   = scr + OFF_B0;
    float* B1   = scr + OFF_B1;
    float* SB   = scr + OFF_SB;

    // 692672 total prep elements -> 2706 blocks of 256
    k_prep<<<2706, 256>>>(tarc, l0f_Wih, l0b_Wih, l1f_Wih, l1b_Wih,
                          ehW, emW, lmW, lhW,
                          l0f_b, l0b_b, l1f_b, l1b_b, ehb, emb, lmb, lhb,
                          l0f_Whh, l0b_Whh, l1f_Whh, l1b_Whh);
    k_embed<<<4096, 128>>>(wid, uid, wl, tl);

    cudaFuncSetAttribute(k_scan, cudaFuncAttributeMaxDynamicSharedMemorySize, SCAN_SMEM);

    k_gemm<<<dim3(8, 64, 2), 256>>>(WORDS, WIH0, B0, XG0F, 500, 128,
                                    512 * 128, 512, 2048000LL);
    k_scan<<<64, 512, SCAN_SMEM>>>(XG0F, XG0B, wpk, wpk + 32256, H0);
    k_gemm<<<dim3(8, 64, 2), 256>>>(H0, WIH1, B1, XG1F, 500, 256,
                                    512 * 256, 512, 2048000LL);
    k_scan<<<64, 512, SCAN_SMEM>>>(XG1F, XG1B, wpk + 2 * 32256, wpk + 3 * 32256, WE1);
    k_gemm<<<dim3(7, 64, 1), 256>>>(WE1, SW, SB, SCOR, 400, 256, 0, 0, 0LL);

    cudaFuncSetAttribute(k_arc, cudaFuncAttributeMaxDynamicSharedMemorySize, 60000);
    k_arc<<<dim3(8, 32), 256, 58656>>>(esW, esb, out + 8192, out);
    k_rel<<<4096, 64>>>(lsW, lsb, out + 532480, out + 4096);
}

// round 12
// speedup vs baseline: 1.0080x; 1.0080x over previous
#include <cuda_runtime.h>
#include <cstdint>
#include <math.h>

typedef unsigned long long ULL;

// ---------------- scratch offsets (floats) ----------------
#define OFF_WORDS 0ull                               // 4096*128
#define OFF_XG0F (OFF_WORDS + 524288ull)             // 4096*500
#define OFF_XG0B (OFF_XG0F + 2048000ull)
#define OFF_XG1F (OFF_XG0B + 2048000ull)
#define OFF_XG1B (OFF_XG1F + 2048000ull)
#define OFF_H0   (OFF_XG1B + 2048000ull)             // 4096*256
#define OFF_WE1  (OFF_H0   + 1048576ull)             // 4096*256
#define OFF_SCOR (OFF_WE1  + 1048576ull)             // 4096*400
#define OFF_WIH0 (OFF_SCOR + 1638400ull)             // 2*512*128
#define OFF_WIH1 (OFF_WIH0 + 131072ull)              // 2*512*256
#define OFF_SW   (OFF_WIH1 + 262144ull)              // 448*256
#define OFF_B0   (OFF_SW   + 114688ull)              // 2*512
#define OFF_B1   (OFF_B0   + 1024ull)                // 2*512
#define OFF_SB   (OFF_B1   + 1024ull)                // 448
#define SCR_TOT  (OFF_SB   + 448ull)

__device__ float g_scr[SCR_TOT];
__device__ int   g_tree[4096];
__device__ int   g_gidx[4096];
__device__ ULL   g_wpk[4 * 63 * 512];   // packed Whh pair image [ld][63][512], rows PERMUTED

// ---------------- f32x2 helpers ----------------
__device__ __forceinline__ ULL pk2(float x, float y) {
    ULL r; asm("mov.b64 %0,{%1,%2};" : "=l"(r) : "f"(x), "f"(y)); return r;
}
__device__ __forceinline__ float2 upk2(ULL v) {
    float2 r; asm("mov.b64 {%0,%1},%2;" : "=f"(r.x), "=f"(r.y) : "l"(v)); return r;
}
__device__ __forceinline__ void fma2(ULL& c, ULL a, ULL b) {
    asm("fma.rn.f32x2 %0,%1,%2,%0;" : "+l"(c) : "l"(a), "l"(b));
}
__device__ __forceinline__ float sig_f(float x) {
    x = fminf(15.f, fmaxf(-15.f, x));
    float e; asm("ex2.approx.f32 %0,%1;" : "=f"(e) : "f"(-1.4426950408889634f * x));
    float r; asm("rcp.approx.f32 %0,%1;" : "=f"(r) : "f"(1.f + e));
    return r;
}
__device__ __forceinline__ float tanh_f(float x) {
    x = fminf(15.f, fmaxf(-15.f, x));
    float e; asm("ex2.approx.f32 %0,%1;" : "=f"(e) : "f"(2.885390081777927f * x));
    float r; asm("rcp.approx.f32 %0,%1;" : "=f"(r) : "f"(e + 1.f));
    return (e - 1.f) * r;
}
__device__ __forceinline__ uint32_t sa(const void* p) {
    return (uint32_t)__cvta_generic_to_shared(p);
}

// ---------------- prep: pack/pad weights, biases, tree/gidx, Whh image ----------------
// g_wpk slot r holds weight row (r&3)*125 + (r>>2)  (gate-interleaved cell order)
__global__ void k_prep(const int* __restrict__ tarc,
                       const float* __restrict__ l0fW, const float* __restrict__ l0bW,
                       const float* __restrict__ l1fW, const float* __restrict__ l1bW,
                       const float* __restrict__ ehW, const float* __restrict__ emW,
                       const float* __restrict__ lmW, const float* __restrict__ lhW,
                       const float* __restrict__ l0fb, const float* __restrict__ l0bb,
                       const float* __restrict__ l1fb, const float* __restrict__ l1bb,
                       const float* __restrict__ ehb, const float* __restrict__ emb,
                       const float* __restrict__ lmb, const float* __restrict__ lhb,
                       const float* __restrict__ whl0f, const float* __restrict__ whl0b,
                       const float* __restrict__ whl1f, const float* __restrict__ whl1b) {
    int idx = blockIdx.x * 256 + threadIdx.x;
    const int E0 = 131072, E1 = E0 + 262144, E2 = E1 + 114688, E3 = E2 + 1024,
              E4 = E3 + 1024, E5 = E4 + 448, E6 = E5 + 4096, E7 = E6 + 24576,
              E8 = E7 + 24576, E9 = E8 + 129024;
    if (idx < E0) {                       // WIH0 [2][512][128]
        int z = idx >> 16, r = idx & 65535, n = r >> 7, k = r & 127;
        const float* s = z ? l0bW : l0fW;
        g_scr[OFF_WIH0 + idx] = (n < 500 && k < 125) ? s[n * 125 + k] : 0.f;
    } else if (idx < E1) {                // WIH1 [2][512][256]
        int i = idx - E0, z = i >> 17, r = i & 131071, n = r >> 8, k = r & 255;
        const float* s = z ? l1bW : l1fW;
        g_scr[OFF_WIH1 + i] = (n < 500 && k < 250) ? s[n * 250 + k] : 0.f;
    } else if (idx < E2) {                // SW [448][256]
        int i = idx - E1, n = i >> 8, k = i & 255;
        float v = 0.f;
        if (k < 250 && n < 400) {
            int sel = n / 100, nn = n - sel * 100;
            const float* s = sel == 0 ? ehW : sel == 1 ? emW : sel == 2 ? lmW : lhW;
            v = s[nn * 250 + k];
        }
        g_scr[OFF_SW + i] = v;
    } else if (idx < E3) {                // B0 [2][512]
        int i = idx - E2, z = i >> 9, n = i & 511;
        g_scr[OFF_B0 + i] = (n < 500) ? (z ? l0bb[n] : l0fb[n]) : 0.f;
    } else if (idx < E4) {                // B1 [2][512]
        int i = idx - E3, z = i >> 9, n = i & 511;
        g_scr[OFF_B1 + i] = (n < 500) ? (z ? l1bb[n] : l1fb[n]) : 0.f;
    } else if (idx < E5) {                // SB [448]
        int n = idx - E4;
        float v = 0.f;
        if (n < 400) {
            int sel = n / 100, nn = n - sel * 100;
            v = sel == 0 ? ehb[nn] : sel == 1 ? emb[nn] : sel == 2 ? lmb[nn] : lhb[nn];
        }
        g_scr[OFF_SB + n] = v;
    } else if (idx < E6) {                // tree + gidx
        int m = idx - E5;
        int v = ((m & 127) == 0) ? 0 : tarc[m];
        g_tree[m] = v;
        g_gidx[m] = (m >> 7) * 128 + v;
    } else if (idx < E7) {                // H0 pad cols 250..255
        int i = idx - E6, m = i / 6, c = i - m * 6;
        g_scr[OFF_H0 + (size_t)m * 256 + 250 + c] = 0.f;
    } else if (idx < E8) {                // WE1 pad cols
        int i = idx - E7, m = i / 6, c = i - m * 6;
        g_scr[OFF_WE1 + (size_t)m * 256 + 250 + c] = 0.f;
    } else if (idx < E9) {                // g_wpk [4][63][512], permuted rows
        int i = idx - E8;
        int ld = i / 32256, rem = i - ld * 32256;
        int k = rem >> 9, r = rem & 511;
        const float* s = ld == 0 ? whl0f : ld == 1 ? whl0b : ld == 2 ? whl1f : whl1b;
        float w0 = 0.f, w1 = 0.f;
        int cell = r >> 2;
        if (cell < 125) {
            int row = (r & 3) * 125 + cell;      // gate-interleaved permutation
            int c0 = 2 * k, c1 = 2 * k + 1;
            if (c0 < 125) w0 = s[row * 125 + c0];
            if (c1 < 125) w1 = s[row * 125 + c1];
        }
        g_wpk[i] = pk2(w0, w1);
    }
}

// ---------------- embedding gather: words[4096,128] (padded) ----------------
__global__ void k_embed(const int* __restrict__ wid, const int* __restrict__ uid,
                        const float* __restrict__ wl, const float* __restrict__ tl) {
    int m = blockIdx.x, t = threadIdx.x;
    float* w = g_scr + OFF_WORDS + (size_t)m * 128;
    float v = 0.f;
    if (t < 100)      v = wl[(size_t)wid[m] * 100 + t];
    else if (t < 125) v = tl[(size_t)uid[m] * 25 + (t - 100)];
    w[t] = v;
}

// ---------------- GEMM (R8 version): C = A @ W^T + bias, m-paired f32x2 ----------------
__global__ void __launch_bounds__(256) k_gemm(const float* __restrict__ A,
                                              const float* __restrict__ Wp,
                                              const float* __restrict__ Bp,
                                              float* __restrict__ C,
                                              int N, int K, int ldWz, int bstride,
                                              long long zsC) {
    __shared__ __align__(16) float As[32][68];
    __shared__ __align__(16) float Ws[32][68];
    int z = blockIdx.z;
    const float* Wz = Wp + (size_t)z * ldWz;
    const float* bz = Bp + (size_t)z * bstride;
    float* Cz = C + (size_t)z * zsC;
    int t = threadIdx.x, tx = t & 15, ty = t >> 4;
    int m0 = blockIdx.y * 64, n0 = blockIdx.x * 64;
    int mf = t >> 3, kg = t & 7;

    ULL acc[2][4];
#pragma unroll
    for (int i = 0; i < 2; i++)
#pragma unroll
        for (int j = 0; j < 4; j++) acc[i][j] = 0ull;

    uint32_t aAddr = sa(&As[0][ty * 4]);

    for (int k0 = 0; k0 < K; k0 += 32) {
        float4 av1 = *(const float4*)(A  + (size_t)(m0 + mf) * K + k0 + kg * 4);
        float4 av2 = *(const float4*)(A  + (size_t)(m0 + mf + 32) * K + k0 + kg * 4);
        float4 wv1 = *(const float4*)(Wz + (size_t)(n0 + mf) * K + k0 + kg * 4);
        float4 wv2 = *(const float4*)(Wz + (size_t)(n0 + mf + 32) * K + k0 + kg * 4);
        As[kg * 4 + 0][mf] = av1.x; As[kg * 4 + 1][mf] = av1.y;
        As[kg * 4 + 2][mf] = av1.z; As[kg * 4 + 3][mf] = av1.w;
        As[kg * 4 + 0][mf + 32] = av2.x; As[kg * 4 + 1][mf + 32] = av2.y;
        As[kg * 4 + 2][mf + 32] = av2.z; As[kg * 4 + 3][mf + 32] = av2.w;
        Ws[kg * 4 + 0][mf] = wv1.x; Ws[kg * 4 + 1][mf] = wv1.y;
        Ws[kg * 4 + 2][mf] = wv1.z; Ws[kg * 4 + 3][mf] = wv1.w;
        Ws[kg * 4 + 0][mf + 32] = wv2.x; Ws[kg * 4 + 1][mf + 32] = wv2.y;
        Ws[kg * 4 + 2][mf + 32] = wv2.z; Ws[kg * 4 + 3][mf + 32] = wv2.w;
        __syncthreads();
#pragma unroll
        for (int k = 0; k < 32; k++) {
            ULL a01, a23;
            asm volatile("ld.shared.v2.u64 {%0,%1},[%2];"
                         : "=l"(a01), "=l"(a23) : "r"(aAddr + k * 272));
            float4 wv = *(const float4*)&Ws[k][tx * 4];
            ULL w0 = pk2(wv.x, wv.x), w1 = pk2(wv.y, wv.y);
            ULL w2 = pk2(wv.z, wv.z), w3 = pk2(wv.w, wv.w);
            fma2(acc[0][0], a01, w0); fma2(acc[1][0], a23, w0);
            fma2(acc[0][1], a01, w1); fma2(acc[1][1], a23, w1);
            fma2(acc[0][2], a01, w2); fma2(acc[1][2], a23, w2);
            fma2(acc[0][3], a01, w3); fma2(acc[1][3], a23, w3);
        }
        __syncthreads();
    }
    int n = n0 + tx * 4;
    float b0 = (n     < N) ? bz[n]     : 0.f;
    float b1 = (n + 1 < N) ? bz[n + 1] : 0.f;
    float b2 = (n + 2 < N) ? bz[n + 2] : 0.f;
    float b3 = (n + 3 < N) ? bz[n + 3] : 0.f;
#pragma unroll
    for (int i = 0; i < 2; i++) {
        float2 t0 = upk2(acc[i][0]), t1 = upk2(acc[i][1]);
        float2 t2 = upk2(acc[i][2]), t3 = upk2(acc[i][3]);
#pragma unroll
        for (int rr = 0; rr < 2; rr++) {
            int m = m0 + ty * 4 + i * 2 + rr;
            float4 v = rr ? make_float4(t0.y + b0, t1.y + b1, t2.y + b2, t3.y + b3)
                          : make_float4(t0.x + b0, t1.x + b1, t2.x + b2, t3.x + b3);
            if (n + 3 < N) {
                *(float4*)(Cz + (size_t)m * N + n) = v;
            } else {
                float vv[4] = {v.x, v.y, v.z, v.w};
                for (int jj = 0; jj < 4; jj++)
                    if (n + jj < N) Cz[(size_t)m * N + n + jj] = vv[jj];
            }
        }
    }
}

// ---------------- LSTM scan: ONE CTA per (b,dir), ONE barrier per step ----------------
// Thread t: gate q=t&3, cell j=t>>2 (4 gates of a cell in adjacent lanes).
// Gates exchanged via width-4 shuffles; h double-buffered in smem.
// Weights: 44 pairs in regs, 19 pairs streamed from smem (permuted wpk image).
#define SPAIR 19
#define SCAN_SMEM (SPAIR * 512 * 8 + 2 * 128 * 4)
__global__ void __launch_bounds__(512, 1)
k_scan(const float* __restrict__ xgf, const float* __restrict__ xgb,
       const ULL* __restrict__ wpkF, const ULL* __restrict__ wpkB,
       float* __restrict__ hout) {
    extern __shared__ __align__(16) char dyn[];
    ULL*   wsp = (ULL*)dyn;                           // [SPAIR][512]
    float* hb  = (float*)(dyn + SPAIR * 512 * 8);     // [2][128]
    int bid = blockIdx.x;
    int b = bid & 31, dir = bid >> 5;
    const float* xg = dir ? xgb : xgf;
    const ULL* wpk  = dir ? wpkB : wpkF;
    int t = threadIdx.x;
    int q = t & 3, j = t >> 2;
    bool act = j < 125;
    int grow = q * 125 + (act ? j : 0);

    ULL wreg[44];
#pragma unroll
    for (int k = 0; k < 44; k++)
        wreg[k] = wpk[k * 512 + t];
#pragma unroll
    for (int k = 0; k < SPAIR; k++)
        wsp[k * 512 + t] = wpk[(44 + k) * 512 + t];
    if (t < 256) hb[t] = 0.f;
    __syncthreads();

    uint32_t hBase = sa(hb);
    uint32_t wA = sa(wsp) + (uint32_t)t * 8;
    float c = 0.f;
    const size_t brow = (size_t)b * 128;
    float xvc = act ? xg[(brow + (dir ? 127 : 0)) * 500 + grow] : 0.f;
    float xvn = act ? xg[(brow + (dir ? 126 : 1)) * 500 + grow] : 0.f;

    for (int s = 0; s < 128; s++) {
        int tt = dir ? (127 - s) : s;
        int par = s & 1;
        uint32_t hA = hBase + (par << 9);
        ULL a0 = 0ull, a1 = 0ull, a2 = 0ull, a3 = 0ull;
        // cols 0..87 from registers
#pragma unroll
        for (int i = 0; i < 22; i++) {
            ULL h01, h23;
            asm volatile("ld.shared.v2.u64 {%0,%1},[%2];"
                         : "=l"(h01), "=l"(h23) : "r"(hA + i * 16));
            if (i & 1) { fma2(a2, h01, wreg[2 * i]); fma2(a3, h23, wreg[2 * i + 1]); }
            else       { fma2(a0, h01, wreg[2 * i]); fma2(a1, h23, wreg[2 * i + 1]); }
        }
        // cols 88..123 from smem pairs
#pragma unroll
        for (int i = 0; i < 9; i++) {
            ULL h01, h23, w01, w23;
            asm volatile("ld.shared.v2.u64 {%0,%1},[%2];"
                         : "=l"(h01), "=l"(h23) : "r"(hA + 352 + i * 16));
            asm volatile("ld.shared.u64 %0,[%1];"
                         : "=l"(w01) : "r"(wA + (2 * i) * 4096));
            asm volatile("ld.shared.u64 %0,[%1];"
                         : "=l"(w23) : "r"(wA + (2 * i + 1) * 4096));
            if (i & 1) { fma2(a2, h01, w01); fma2(a3, h23, w23); }
            else       { fma2(a0, h01, w01); fma2(a1, h23, w23); }
        }
        // cols 124..125 (h[125..127]==0, weight col125 packed as 0)
        {
            ULL h01, w01;
            asm volatile("ld.shared.u64 %0,[%1];" : "=l"(h01) : "r"(hA + 496));
            asm volatile("ld.shared.u64 %0,[%1];" : "=l"(w01) : "r"(wA + 18 * 4096));
            fma2(a0, h01, w01);
        }
        float2 f0 = upk2(a0), f1 = upk2(a1), f2 = upk2(a2), f3 = upk2(a3);
        float g = ((f0.x + f0.y) + (f1.x + f1.y)) + ((f2.x + f2.y) + (f3.x + f3.y)) + xvc;
        float val = (q == 2) ? tanh_f(g) : sig_f(g);
        // width-4 gate exchange (warp-synchronous, no smem round trip)
        float si = __shfl_sync(0xffffffffu, val, 0, 4);
        float sf = __shfl_sync(0xffffffffu, val, 1, 4);
        float tg = __shfl_sync(0xffffffffu, val, 2, 4);
        float so = __shfl_sync(0xffffffffu, val, 3, 4);
        c = sf * c + si * tg;
        float hh = so * tanh_f(c);
        if (q == 0 && act) {
            hb[(par ^ 1) * 128 + j] = hh;
            hout[(brow + tt) * 256 + dir * 125 + j] = hh;
        }
        xvc = xvn;
        if (s + 2 < 128) {
            int tn = dir ? (125 - s) : (s + 2);
            xvn = act ? xg[(brow + tn) * 500 + grow] : 0.f;
        }
        __syncthreads();
    }
}

// ---------------- biaffine arc scores + margin + argmax ----------------
__global__ void __launch_bounds__(256) k_arc(const float* __restrict__ esW,
                                             const float* __restrict__ esb,
                                             float* __restrict__ arc_out,
                                             float* __restrict__ parsed_out) {
    extern __shared__ float sm[];
    float* wms   = sm;                 // 128*101
    float* whs   = sm + 128 * 101;     // 16*101
    float* esw   = whs + 16 * 101;     // 100
    float* baseS = esw + 100;          // 1
    int*   treei = (int*)(baseS + 1);  // 16
    const float S = 2.885390081777927f; // 2*log2(e)
    int b = blockIdx.y, i0 = blockIdx.x * 16;
    int t = threadIdx.x;
    const float* wm = g_scr + OFF_SCOR + (size_t)b * 128 * 400 + 100;
    const float* wh = g_scr + OFF_SCOR + ((size_t)b * 128 + i0) * 400;
    for (int idx = t; idx < 12800; idx += 256) {
        int j = idx / 100, h = idx - j * 100;
        wms[j * 101 + h] = wm[(size_t)j * 400 + h] * S;
    }
    for (int idx = t; idx < 1600; idx += 256) {
        int ii = idx / 100, h = idx - ii * 100;
        whs[ii * 101 + h] = wh[(size_t)ii * 400 + h] * S;
    }
    if (t < 100) esw[t] = -2.f * esW[t];
    if (t == 0) {
        float ssum = 0.f;
        for (int h = 0; h < 100; h++) ssum += esW[h];
        baseS[0] = ssum + esb[0] + 1.f;
    }
    if (t < 16) treei[t] = g_tree[b * 128 + i0 + t];
    __syncthreads();

    int ii = t >> 4, jl = t & 15;
    int i = i0 + ii;
    int tgt = treei[ii];
    float base = baseS[0];
    float best = -1e30f; int bj = 0;
    float* arow = arc_out + ((size_t)b * 128 + i) * 128;
    const float* Arow = whs + ii * 101;
    for (int jt = 0; jt < 8; jt++) {
        int j = jl + 16 * jt;
        const float* Brow = wms + j * 101;
        float acc = 0.f;
#pragma unroll
        for (int h = 0; h < 100; h++) {
            float x = Arow[h] + Brow[h];
            float e; asm("ex2.approx.f32 %0, %1;" : "=f"(e) : "f"(x));
            float rr; asm("rcp.approx.f32 %0, %1;" : "=f"(rr) : "f"(1.f + e));
            acc = fmaf(esw[h], rr, acc);
        }
        float sc = base + acc - ((j == tgt) ? 1.f : 0.f);
        arow[j] = sc;
        if (sc > best) { best = sc; bj = j; }
    }
    for (int off = 8; off; off >>= 1) {
        float ob = __shfl_xor_sync(0xffffffffu, best, off);
        int   oj = __shfl_xor_sync(0xffffffffu, bj, off);
        if (ob > best || (ob == best && oj < bj)) { best = ob; bj = oj; }
    }
    if (jl == 0) parsed_out[b * 128 + i] = (float)bj;
}

// ---------------- rel scores + argmax (head gather post-projection) ----------------
__global__ void k_rel(const float* __restrict__ lsW, const float* __restrict__ lsb,
                      float* __restrict__ rel_out, float* __restrict__ pred_out) {
    __shared__ float th[100];
    __shared__ float sc[50];
    int m = blockIdx.x, t = threadIdx.x;
    const float* rm = g_scr + OFF_SCOR + (size_t)m * 400 + 200;
    const float* rh = g_scr + OFF_SCOR + (size_t)g_gidx[m] * 400 + 300;
    for (int h = t; h < 100; h += 64) th[h] = tanhf(rm[h] + rh[h]);
    __syncthreads();
    if (t < 50) {
        float acc = lsb[t];
        const float* wr = lsW + t * 100;
#pragma unroll 10
        for (int h = 0; h < 100; h++) acc = fmaf(th[h], wr[h], acc);
        rel_out[(size_t)m * 50 + t] = acc;
        sc[t] = acc;
    }
    __syncthreads();
    if (t == 0) {
        float best = sc[0]; int bl = 0;
        for (int l = 1; l < 50; l++) if (sc[l] > best) { best = sc[l]; bl = l; }
        pred_out[m] = (float)bl;
    }
}

// ---------------- launch ----------------
extern "C" void kernel_launch(void* const* d_in, const int* in_sizes, int n_in,
                              void* d_out, int out_size) {
    const int* wid  = (const int*)d_in[0];
    const int* uid  = (const int*)d_in[1];
    const int* tarc = (const int*)d_in[2];
    const float* wl = (const float*)d_in[3];
    const float* tl = (const float*)d_in[4];
    const float* l0f_Wih = (const float*)d_in[5];
    const float* l0f_Whh = (const float*)d_in[6];
    const float* l0f_b   = (const float*)d_in[7];
    const float* l0b_Wih = (const float*)d_in[8];
    const float* l0b_Whh = (const float*)d_in[9];
    const float* l0b_b   = (const float*)d_in[10];
    const float* l1f_Wih = (const float*)d_in[11];
    const float* l1f_Whh = (const float*)d_in[12];
    const float* l1f_b   = (const float*)d_in[13];
    const float* l1b_Wih = (const float*)d_in[14];
    const float* l1b_Whh = (const float*)d_in[15];
    const float* l1b_b   = (const float*)d_in[16];
    const float* ehW = (const float*)d_in[17];
    const float* ehb = (const float*)d_in[18];
    const float* emW = (const float*)d_in[19];
    const float* emb = (const float*)d_in[20];
    const float* esW = (const float*)d_in[21];
    const float* esb = (const float*)d_in[22];
    const float* lhW = (const float*)d_in[23];
    const float* lhb = (const float*)d_in[24];
    const float* lmW = (const float*)d_in[25];
    const float* lmb = (const float*)d_in[26];
    const float* lsW = (const float*)d_in[27];
    const float* lsb = (const float*)d_in[28];
    float* out = (float*)d_out;

    float* scr = nullptr;
    cudaGetSymbolAddress((void**)&scr, g_scr);
    ULL* wpk = nullptr;
    cudaGetSymbolAddress((void**)&wpk, g_wpk);
    float* WORDS = scr + OFF_WORDS;
    float* XG0F = scr + OFF_XG0F;
    float* XG0B = scr + OFF_XG0B;
    float* XG1F = scr + OFF_XG1F;
    float* XG1B = scr + OFF_XG1B;
    float* H0   = scr + OFF_H0;
    float* WE1  = scr + OFF_WE1;
    float* SCOR = scr + OFF_SCOR;
    float* WIH0 = scr + OFF_WIH0;
    float* WIH1 = scr + OFF_WIH1;
    float* SW   = scr + OFF_SW;
    float* B0   = scr + OFF_B0;
    float* B1   = scr + OFF_B1;
    float* SB   = scr + OFF_SB;

    // 692672 total prep elements -> 2706 blocks of 256
    k_prep<<<2706, 256>>>(tarc, l0f_Wih, l0b_Wih, l1f_Wih, l1b_Wih,
                          ehW, emW, lmW, lhW,
                          l0f_b, l0b_b, l1f_b, l1b_b, ehb, emb, lmb, lhb,
                          l0f_Whh, l0b_Whh, l1f_Whh, l1b_Whh);
    k_embed<<<4096, 128>>>(wid, uid, wl, tl);

    cudaFuncSetAttribute(k_scan, cudaFuncAttributeMaxDynamicSharedMemorySize, SCAN_SMEM);

    k_gemm<<<dim3(8, 64, 2), 256>>>(WORDS, WIH0, B0, XG0F, 500, 128,
                                    512 * 128, 512, 2048000LL);
    k_scan<<<64, 512, SCAN_SMEM>>>(XG0F, XG0B, wpk, wpk + 32256, H0);
    k_gemm<<<dim3(8, 64, 2), 256>>>(H0, WIH1, B1, XG1F, 500, 256,
                                    512 * 256, 512, 2048000LL);
    k_scan<<<64, 512, SCAN_SMEM>>>(XG1F, XG1B, wpk + 2 * 32256, wpk + 3 * 32256, WE1);
    k_gemm<<<dim3(7, 64, 1), 256>>>(WE1, SW, SB, SCOR, 400, 256, 0, 0, 0LL);

    cudaFuncSetAttribute(k_arc, cudaFuncAttributeMaxDynamicSharedMemorySize, 60000);
    k_arc<<<dim3(8, 32), 256, 58656>>>(esW, esb, out + 8192, out);
    k_rel<<<4096, 64>>>(lsW, lsb, out + 532480, out + 4096);
}

// round 14
// speedup vs baseline: 1.0753x; 1.0668x over previous
#include <cuda_runtime.h>
#include <cstdint>
#include <math.h>

typedef unsigned long long ULL;

// ---------------- scratch offsets (floats) ----------------
#define OFF_WORDS 0ull                               // 4096*128
#define OFF_XG0F (OFF_WORDS + 524288ull)             // 4096*500
#define OFF_XG0B (OFF_XG0F + 2048000ull)
#define OFF_XG1F (OFF_XG0B + 2048000ull)
#define OFF_XG1B (OFF_XG1F + 2048000ull)
#define OFF_H0   (OFF_XG1B + 2048000ull)             // 4096*256
#define OFF_WE1  (OFF_H0   + 1048576ull)             // 4096*256
#define OFF_SCOR (OFF_WE1  + 1048576ull)             // 4096*400
#define OFF_WIH0 (OFF_SCOR + 1638400ull)             // 2*512*128
#define OFF_WIH1 (OFF_WIH0 + 131072ull)              // 2*512*256
#define OFF_SW   (OFF_WIH1 + 262144ull)              // 448*256
#define OFF_B0   (OFF_SW   + 114688ull)              // 2*512
#define OFF_B1   (OFF_B0   + 1024ull)                // 2*512
#define OFF_SB   (OFF_B1   + 1024ull)                // 448
#define SCR_TOT  (OFF_SB   + 448ull)

__device__ float g_scr[SCR_TOT];
__device__ int   g_tree[4096];
__device__ int   g_gidx[4096];
__device__ ULL   g_wpk[4 * 63 * 512];   // packed Whh pair image [ld][63][512]

// ---------------- f32x2 helpers ----------------
__device__ __forceinline__ ULL pk2(float x, float y) {
    ULL r; asm("mov.b64 %0,{%1,%2};" : "=l"(r) : "f"(x), "f"(y)); return r;
}
__device__ __forceinline__ float2 upk2(ULL v) {
    float2 r; asm("mov.b64 {%0,%1},%2;" : "=f"(r.x), "=f"(r.y) : "l"(v)); return r;
}
__device__ __forceinline__ void fma2(ULL& c, ULL a, ULL b) {
    asm("fma.rn.f32x2 %0,%1,%2,%0;" : "+l"(c) : "l"(a), "l"(b));
}
__device__ __forceinline__ float sig_f(float x) {
    x = fminf(15.f, fmaxf(-15.f, x));
    float e; asm("ex2.approx.f32 %0,%1;" : "=f"(e) : "f"(-1.4426950408889634f * x));
    float r; asm("rcp.approx.f32 %0,%1;" : "=f"(r) : "f"(1.f + e));
    return r;
}
__device__ __forceinline__ float tanh_f(float x) {
    x = fminf(15.f, fmaxf(-15.f, x));
    float e; asm("ex2.approx.f32 %0,%1;" : "=f"(e) : "f"(2.885390081777927f * x));
    float r; asm("rcp.approx.f32 %0,%1;" : "=f"(r) : "f"(e + 1.f));
    return (e - 1.f) * r;
}
__device__ __forceinline__ uint32_t sa(const void* p) {
    return (uint32_t)__cvta_generic_to_shared(p);
}

// ---------------- prep: pack/pad weights, biases, tree/gidx, Whh image ----------------
__global__ void k_prep(const int* __restrict__ tarc,
                       const float* __restrict__ l0fW, const float* __restrict__ l0bW,
                       const float* __restrict__ l1fW, const float* __restrict__ l1bW,
                       const float* __restrict__ ehW, const float* __restrict__ emW,
                       const float* __restrict__ lmW, const float* __restrict__ lhW,
                       const float* __restrict__ l0fb, const float* __restrict__ l0bb,
                       const float* __restrict__ l1fb, const float* __restrict__ l1bb,
                       const float* __restrict__ ehb, const float* __restrict__ emb,
                       const float* __restrict__ lmb, const float* __restrict__ lhb,
                       const float* __restrict__ whl0f, const float* __restrict__ whl0b,
                       const float* __restrict__ whl1f, const float* __restrict__ whl1b) {
    int idx = blockIdx.x * 256 + threadIdx.x;
    const int E0 = 131072, E1 = E0 + 262144, E2 = E1 + 114688, E3 = E2 + 1024,
              E4 = E3 + 1024, E5 = E4 + 448, E6 = E5 + 4096, E7 = E6 + 24576,
              E8 = E7 + 24576, E9 = E8 + 129024;
    if (idx < E0) {                       // WIH0 [2][512][128]
        int z = idx >> 16, r = idx & 65535, n = r >> 7, k = r & 127;
        const float* s = z ? l0bW : l0fW;
        g_scr[OFF_WIH0 + idx] = (n < 500 && k < 125) ? s[n * 125 + k] : 0.f;
    } else if (idx < E1) {                // WIH1 [2][512][256]
        int i = idx - E0, z = i >> 17, r = i & 131071, n = r >> 8, k = r & 255;
        const float* s = z ? l1bW : l1fW;
        g_scr[OFF_WIH1 + i] = (n < 500 && k < 250) ? s[n * 250 + k] : 0.f;
    } else if (idx < E2) {                // SW [448][256]
        int i = idx - E1, n = i >> 8, k = i & 255;
        float v = 0.f;
        if (k < 250 && n < 400) {
            int sel = n / 100, nn = n - sel * 100;
            const float* s = sel == 0 ? ehW : sel == 1 ? emW : sel == 2 ? lmW : lhW;
            v = s[nn * 250 + k];
        }
        g_scr[OFF_SW + i] = v;
    } else if (idx < E3) {                // B0 [2][512]
        int i = idx - E2, z = i >> 9, n = i & 511;
        g_scr[OFF_B0 + i] = (n < 500) ? (z ? l0bb[n] : l0fb[n]) : 0.f;
    } else if (idx < E4) {                // B1 [2][512]
        int i = idx - E3, z = i >> 9, n = i & 511;
        g_scr[OFF_B1 + i] = (n < 500) ? (z ? l1bb[n] : l1fb[n]) : 0.f;
    } else if (idx < E5) {                // SB [448]
        int n = idx - E4;
        float v = 0.f;
        if (n < 400) {
            int sel = n / 100, nn = n - sel * 100;
            v = sel == 0 ? ehb[nn] : sel == 1 ? emb[nn] : sel == 2 ? lmb[nn] : lhb[nn];
        }
        g_scr[OFF_SB + n] = v;
    } else if (idx < E6) {                // tree + gidx
        int m = idx - E5;
        int v = ((m & 127) == 0) ? 0 : tarc[m];
        g_tree[m] = v;
        g_gidx[m] = (m >> 7) * 128 + v;
    } else if (idx < E7) {                // H0 pad cols 250..255
        int i = idx - E6, m = i / 6, c = i - m * 6;
        g_scr[OFF_H0 + (size_t)m * 256 + 250 + c] = 0.f;
    } else if (idx < E8) {                // WE1 pad cols
        int i = idx - E7, m = i / 6, c = i - m * 6;
        g_scr[OFF_WE1 + (size_t)m * 256 + 250 + c] = 0.f;
    } else if (idx < E9) {                // g_wpk [4][63][512]
        int i = idx - E8;
        int ld = i / 32256, rem = i - ld * 32256;
        int k = rem >> 9, r = rem & 511;
        const float* s = ld == 0 ? whl0f : ld == 1 ? whl0b : ld == 2 ? whl1f : whl1b;
        float w0 = 0.f, w1 = 0.f;
        if (r < 500) {
            int c0 = 2 * k, c1 = 2 * k + 1;
            if (c0 < 125) w0 = s[r * 125 + c0];
            if (c1 < 125) w1 = s[r * 125 + c1];
        }
        g_wpk[i] = pk2(w0, w1);
    }
}

// ---------------- embedding gather: words[4096,128] (padded) ----------------
__global__ void k_embed(const int* __restrict__ wid, const int* __restrict__ uid,
                        const float* __restrict__ wl, const float* __restrict__ tl) {
    int m = blockIdx.x, t = threadIdx.x;
    float* w = g_scr + OFF_WORDS + (size_t)m * 128;
    float v = 0.f;
    if (t < 100)      v = wl[(size_t)wid[m] * 100 + t];
    else if (t < 125) v = tl[(size_t)uid[m] * 25 + (t - 100)];
    w[t] = v;
}

// ---------------- GEMM: double-buffered smem, ONE barrier per k-iter ----------------
__global__ void __launch_bounds__(256) k_gemm(const float* __restrict__ A,
                                              const float* __restrict__ Wp,
                                              const float* __restrict__ Bp,
                                              float* __restrict__ C,
                                              int N, int K, int ldWz, int bstride,
                                              long long zsC) {
    __shared__ __align__(16) float As[2][32][68];
    __shared__ __align__(16) float Ws[2][32][68];
    int z = blockIdx.z;
    const float* Wz = Wp + (size_t)z * ldWz;
    const float* bz = Bp + (size_t)z * bstride;
    float* Cz = C + (size_t)z * zsC;
    int t = threadIdx.x, tx = t & 15, ty = t >> 4;
    int m0 = blockIdx.y * 64, n0 = blockIdx.x * 64;
    int mf = t >> 3, kg = t & 7;

    ULL acc[2][4];
#pragma unroll
    for (int i = 0; i < 2; i++)
#pragma unroll
        for (int j = 0; j < 4; j++) acc[i][j] = 0ull;

    uint32_t aBase = sa(&As[0][0][ty * 4]);
    const int BUFB = 32 * 68 * 4;           // bytes per buffer

    // prologue: tile 0 -> buffer 0
    {
        float4 av1 = *(const float4*)(A  + (size_t)(m0 + mf) * K + kg * 4);
        float4 av2 = *(const float4*)(A  + (size_t)(m0 + mf + 32) * K + kg * 4);
        float4 wv1 = *(const float4*)(Wz + (size_t)(n0 + mf) * K + kg * 4);
        float4 wv2 = *(const float4*)(Wz + (size_t)(n0 + mf + 32) * K + kg * 4);
        As[0][kg * 4 + 0][mf] = av1.x; As[0][kg * 4 + 1][mf] = av1.y;
        As[0][kg * 4 + 2][mf] = av1.z; As[0][kg * 4 + 3][mf] = av1.w;
        As[0][kg * 4 + 0][mf + 32] = av2.x; As[0][kg * 4 + 1][mf + 32] = av2.y;
        As[0][kg * 4 + 2][mf + 32] = av2.z; As[0][kg * 4 + 3][mf + 32] = av2.w;
        Ws[0][kg * 4 + 0][mf] = wv1.x; Ws[0][kg * 4 + 1][mf] = wv1.y;
        Ws[0][kg * 4 + 2][mf] = wv1.z; Ws[0][kg * 4 + 3][mf] = wv1.w;
        Ws[0][kg * 4 + 0][mf + 32] = wv2.x; Ws[0][kg * 4 + 1][mf + 32] = wv2.y;
        Ws[0][kg * 4 + 2][mf + 32] = wv2.z; Ws[0][kg * 4 + 3][mf + 32] = wv2.w;
    }
    __syncthreads();

    int nIter = K >> 5;
    for (int it = 0; it < nIter; it++) {
        int cur = it & 1;
        float4 av1, av2, wv1, wv2;
        bool more = (it + 1 < nIter);
        if (more) {
            int k0 = (it + 1) << 5;
            av1 = *(const float4*)(A  + (size_t)(m0 + mf) * K + k0 + kg * 4);
            av2 = *(const float4*)(A  + (size_t)(m0 + mf + 32) * K + k0 + kg * 4);
            wv1 = *(const float4*)(Wz + (size_t)(n0 + mf) * K + k0 + kg * 4);
            wv2 = *(const float4*)(Wz + (size_t)(n0 + mf + 32) * K + k0 + kg * 4);
        }
        uint32_t aAddr = aBase + cur * BUFB;
#pragma unroll
        for (int k = 0; k < 32; k++) {
            ULL a01, a23;
            asm volatile("ld.shared.v2.u64 {%0,%1},[%2];"
                         : "=l"(a01), "=l"(a23) : "r"(aAddr + k * 272));
            float4 wv = *(const float4*)&Ws[cur][k][tx * 4];
            ULL w0 = pk2(wv.x, wv.x), w1 = pk2(wv.y, wv.y);
            ULL w2 = pk2(wv.z, wv.z), w3 = pk2(wv.w, wv.w);
            fma2(acc[0][0], a01, w0); fma2(acc[1][0], a23, w0);
            fma2(acc[0][1], a01, w1); fma2(acc[1][1], a23, w1);
            fma2(acc[0][2], a01, w2); fma2(acc[1][2], a23, w2);
            fma2(acc[0][3], a01, w3); fma2(acc[1][3], a23, w3);
        }
        if (more) {
            int nb = cur ^ 1;
            As[nb][kg * 4 + 0][mf] = av1.x; As[nb][kg * 4 + 1][mf] = av1.y;
            As[nb][kg * 4 + 2][mf] = av1.z; As[nb][kg * 4 + 3][mf] = av1.w;
            As[nb][kg * 4 + 0][mf + 32] = av2.x; As[nb][kg * 4 + 1][mf + 32] = av2.y;
            As[nb][kg * 4 + 2][mf + 32] = av2.z; As[nb][kg * 4 + 3][mf + 32] = av2.w;
            Ws[nb][kg * 4 + 0][mf] = wv1.x; Ws[nb][kg * 4 + 1][mf] = wv1.y;
            Ws[nb][kg * 4 + 2][mf] = wv1.z; Ws[nb][kg * 4 + 3][mf] = wv1.w;
            Ws[nb][kg * 4 + 0][mf + 32] = wv2.x; Ws[nb][kg * 4 + 1][mf + 32] = wv2.y;
            Ws[nb][kg * 4 + 2][mf + 32] = wv2.z; Ws[nb][kg * 4 + 3][mf + 32] = wv2.w;
            __syncthreads();
        }
    }
    int n = n0 + tx * 4;
    float b0 = (n     < N) ? bz[n]     : 0.f;
    float b1 = (n + 1 < N) ? bz[n + 1] : 0.f;
    float b2 = (n + 2 < N) ? bz[n + 2] : 0.f;
    float b3 = (n + 3 < N) ? bz[n + 3] : 0.f;
#pragma unroll
    for (int i = 0; i < 2; i++) {
        float2 t0 = upk2(acc[i][0]), t1 = upk2(acc[i][1]);
        float2 t2 = upk2(acc[i][2]), t3 = upk2(acc[i][3]);
#pragma unroll
        for (int rr = 0; rr < 2; rr++) {
            int m = m0 + ty * 4 + i * 2 + rr;
            float4 v = rr ? make_float4(t0.y + b0, t1.y + b1, t2.y + b2, t3.y + b3)
                          : make_float4(t0.x + b0, t1.x + b1, t2.x + b2, t3.x + b3);
            if (n + 3 < N) {
                *(float4*)(Cz + (size_t)m * N + n) = v;
            } else {
                float vv[4] = {v.x, v.y, v.z, v.w};
                for (int jj = 0; jj < 4; jj++)
                    if (n + jj < N) Cz[(size_t)m * N + n + jj] = vv[jj];
            }
        }
    }
}

// ---------------- LSTM scan (R11 best): ONE CTA per (b,dir) ----------------
#define SPAIR 19
#define SCAN_SMEM (SPAIR * 512 * 8 + 128 * 4 + 512 * 4)
__global__ void __launch_bounds__(512, 1)
k_scan(const float* __restrict__ xgf, const float* __restrict__ xgb,
       const ULL* __restrict__ wpkF, const ULL* __restrict__ wpkB,
       float* __restrict__ hout) {
    extern __shared__ __align__(16) char dyn[];
    ULL*   wsp  = (ULL*)dyn;                          // [SPAIR][512]
    float* h    = (float*)(dyn + SPAIR * 512 * 8);    // [128]
    float* gacc = h + 128;                            // [512]
    int bid = blockIdx.x;
    int b = bid & 31, dir = bid >> 5;
    const float* xg = dir ? xgb : xgf;
    const ULL* wpk  = dir ? wpkB : wpkF;
    int t = threadIdx.x;
    bool act = t < 500;
    int r = act ? t : 0;

    ULL wreg[44];
#pragma unroll
    for (int k = 0; k < 44; k++)
        wreg[k] = wpk[k * 512 + t];
#pragma unroll
    for (int k = 0; k < SPAIR; k++)
        wsp[k * 512 + t] = wpk[(44 + k) * 512 + t];
    if (t < 128) h[t] = 0.f;
    __syncthreads();

    uint32_t hA = sa(h);
    uint32_t wA = sa(wsp) + (uint32_t)t * 8;
    float c = 0.f;
    const size_t brow = (size_t)b * 128;
    float xvc = act ? xg[(brow + (dir ? 127 : 0)) * 500 + r] : 0.f;
    float xvn = act ? xg[(brow + (dir ? 126 : 1)) * 500 + r] : 0.f;
    bool istanh = (t >= 250 && t < 375);

    for (int s = 0; s < 128; s++) {
        int tt = dir ? (127 - s) : s;
        ULL a0 = 0ull, a1 = 0ull, a2 = 0ull, a3 = 0ull;
#pragma unroll
        for (int i = 0; i < 22; i++) {
            ULL h01, h23;
            asm volatile("ld.shared.v2.u64 {%0,%1},[%2];"
                         : "=l"(h01), "=l"(h23) : "r"(hA + i * 16));
            if (i & 1) { fma2(a2, h01, wreg[2 * i]); fma2(a3, h23, wreg[2 * i + 1]); }
            else       { fma2(a0, h01, wreg[2 * i]); fma2(a1, h23, wreg[2 * i + 1]); }
        }
#pragma unroll
        for (int i = 0; i < 9; i++) {
            ULL h01, h23, w01, w23;
            asm volatile("ld.shared.v2.u64 {%0,%1},[%2];"
                         : "=l"(h01), "=l"(h23) : "r"(hA + 352 + i * 16));
            asm volatile("ld.shared.u64 %0,[%1];"
                         : "=l"(w01) : "r"(wA + (2 * i) * 4096));
            asm volatile("ld.shared.u64 %0,[%1];"
                         : "=l"(w23) : "r"(wA + (2 * i + 1) * 4096));
            if (i & 1) { fma2(a2, h01, w01); fma2(a3, h23, w23); }
            else       { fma2(a0, h01, w01); fma2(a1, h23, w23); }
        }
        {
            ULL h01, w01;
            asm volatile("ld.shared.u64 %0,[%1];" : "=l"(h01) : "r"(hA + 496));
            asm volatile("ld.shared.u64 %0,[%1];" : "=l"(w01) : "r"(wA + 18 * 4096));
            fma2(a0, h01, w01);
        }
        float2 f0 = upk2(a0), f1 = upk2(a1), f2 = upk2(a2), f3 = upk2(a3);
        float g = ((f0.x + f0.y) + (f1.x + f1.y)) + ((f2.x + f2.y) + (f3.x + f3.y)) + xvc;
        gacc[t] = istanh ? tanh_f(g) : sig_f(g);
        xvc = xvn;
        if (s + 2 < 128) {
            int tn = dir ? (125 - s) : (s + 2);
            xvn = act ? xg[(brow + tn) * 500 + r] : 0.f;
        }
        __syncthreads();
        if (t < 125) {
            float si = gacc[t], sf = gacc[125 + t], tg = gacc[250 + t], so = gacc[375 + t];
            c = sf * c + si * tg;
            float hh = so * tanh_f(c);
            h[t] = hh;
            hout[(brow + tt) * 256 + dir * 125 + t] = hh;
        }
        __syncthreads();
    }
}

// ---------------- biaffine arc scores + margin + argmax ----------------
__global__ void __launch_bounds__(256) k_arc(const float* __restrict__ esW,
                                             const float* __restrict__ esb,
                                             float* __restrict__ arc_out,
                                             float* __restrict__ parsed_out) {
    extern __shared__ float sm[];
    float* wms   = sm;                 // 128*101
    float* whs   = sm + 128 * 101;     // 16*101
    float* esw   = whs + 16 * 101;     // 100
    float* baseS = esw + 100;          // 1
    int*   treei = (int*)(baseS + 1);  // 16
    const float S = 2.885390081777927f; // 2*log2(e)
    int b = blockIdx.y, i0 = blockIdx.x * 16;
    int t = threadIdx.x;
    const float* wm = g_scr + OFF_SCOR + (size_t)b * 128 * 400 + 100;
    const float* wh = g_scr + OFF_SCOR + ((size_t)b * 128 + i0) * 400;
    for (int idx = t; idx < 12800; idx += 256) {
        int j = idx / 100, h = idx - j * 100;
        wms[j * 101 + h] = wm[(size_t)j * 400 + h] * S;
    }
    for (int idx = t; idx < 1600; idx += 256) {
        int ii = idx / 100, h = idx - ii * 100;
        whs[ii * 101 + h] = wh[(size_t)ii * 400 + h] * S;
    }
    if (t < 100) esw[t] = -2.f * esW[t];
    if (t == 0) {
        float ssum = 0.f;
        for (int h = 0; h < 100; h++) ssum += esW[h];
        baseS[0] = ssum + esb[0] + 1.f;
    }
    if (t < 16) treei[t] = g_tree[b * 128 + i0 + t];
    __syncthreads();

    int ii = t >> 4, jl = t & 15;
    int i = i0 + ii;
    int tgt = treei[ii];
    float base = baseS[0];
    float best = -1e30f; int bj = 0;
    float* arow = arc_out + ((size_t)b * 128 + i) * 128;
    const float* Arow = whs + ii * 101;
    for (int jt = 0; jt < 8; jt++) {
        int j = jl + 16 * jt;
        const float* Brow = wms + j * 101;
        float acc = 0.f;
#pragma unroll
        for (int h = 0; h < 100; h++) {
            float x = Arow[h] + Brow[h];
            float e; asm("ex2.approx.f32 %0, %1;" : "=f"(e) : "f"(x));
            float rr; asm("rcp.approx.f32 %0, %1;" : "=f"(rr) : "f"(1.f + e));
            acc = fmaf(esw[h], rr, acc);
        }
        float sc = base + acc - ((j == tgt) ? 1.f : 0.f);
        arow[j] = sc;
        if (sc > best) { best = sc; bj = j; }
    }
    for (int off = 8; off; off >>= 1) {
        float ob = __shfl_xor_sync(0xffffffffu, best, off);
        int   oj = __shfl_xor_sync(0xffffffffu, bj, off);
        if (ob > best || (ob == best && oj < bj)) { best = ob; bj = oj; }
    }
    if (jl == 0) parsed_out[b * 128 + i] = (float)bj;
}

// ---------------- rel scores + argmax (head gather post-projection) ----------------
__global__ void k_rel(const float* __restrict__ lsW, const float* __restrict__ lsb,
                      float* __restrict__ rel_out, float* __restrict__ pred_out) {
    __shared__ float th[100];
    __shared__ float sc[50];
    int m = blockIdx.x, t = threadIdx.x;
    const float* rm = g_scr + OFF_SCOR + (size_t)m * 400 + 200;
    const float* rh = g_scr + OFF_SCOR + (size_t)g_gidx[m] * 400 + 300;
    for (int h = t; h < 100; h += 64) th[h] = tanhf(rm[h] + rh[h]);
    __syncthreads();
    if (t < 50) {
        float acc = lsb[t];
        const float* wr = lsW + t * 100;
#pragma unroll 10
        for (int h = 0; h < 100; h++) acc = fmaf(th[h], wr[h], acc);
        rel_out[(size_t)m * 50 + t] = acc;
        sc[t] = acc;
    }
    __syncthreads();
    if (t == 0) {
        float best = sc[0]; int bl = 0;
        for (int l = 1; l < 50; l++) if (sc[l] > best) { best = sc[l]; bl = l; }
        pred_out[m] = (float)bl;
    }
}

// ---------------- launch ----------------
extern "C" void kernel_launch(void* const* d_in, const int* in_sizes, int n_in,
                              void* d_out, int out_size) {
    const int* wid  = (const int*)d_in[0];
    const int* uid  = (const int*)d_in[1];
    const int* tarc = (const int*)d_in[2];
    const float* wl = (const float*)d_in[3];
    const float* tl = (const float*)d_in[4];
    const float* l0f_Wih = (const float*)d_in[5];
    const float* l0f_Whh = (const float*)d_in[6];
    const float* l0f_b   = (const float*)d_in[7];
    const float* l0b_Wih = (const float*)d_in[8];
    const float* l0b_Whh = (const float*)d_in[9];
    const float* l0b_b   = (const float*)d_in[10];
    const float* l1f_Wih = (const float*)d_in[11];
    const float* l1f_Whh = (const float*)d_in[12];
    const float* l1f_b   = (const float*)d_in[13];
    const float* l1b_Wih = (const float*)d_in[14];
    const float* l1b_Whh = (const float*)d_in[15];
    const float* l1b_b   = (const float*)d_in[16];
    const float* ehW = (const float*)d_in[17];
    const float* ehb = (const float*)d_in[18];
    const float* emW = (const float*)d_in[19];
    const float* emb = (const float*)d_in[20];
    const float* esW = (const float*)d_in[21];
    const float* esb = (const float*)d_in[22];
    const float* lhW = (const float*)d_in[23];
    const float* lhb = (const float*)d_in[24];
    const float* lmW = (const float*)d_in[25];
    const float* lmb = (const float*)d_in[26];
    const float* lsW = (const float*)d_in[27];
    const float* lsb = (const float*)d_in[28];
    float* out = (float*)d_out;

    float* scr = nullptr;
    cudaGetSymbolAddress((void**)&scr, g_scr);
    ULL* wpk = nullptr;
    cudaGetSymbolAddress((void**)&wpk, g_wpk);
    float* WORDS = scr + OFF_WORDS;
    float* XG0F = scr + OFF_XG0F;
    float* XG0B = scr + OFF_XG0B;
    float* XG1F = scr + OFF_XG1F;
    float* XG1B = scr + OFF_XG1B;
    float* H0   = scr + OFF_H0;
    float* WE1  = scr + OFF_WE1;
    float* SCOR = scr + OFF_SCOR;
    float* WIH0 = scr + OFF_WIH0;
    float* WIH1 = scr + OFF_WIH1;
    float* SW   = scr + OFF_SW;
    float* B0   = scr + OFF_B0;
    float* B1   = scr + OFF_B1;
    float* SB   = scr + OFF_SB;

    // 692672 total prep elements -> 2706 blocks of 256
    k_prep<<<2706, 256>>>(tarc, l0f_Wih, l0b_Wih, l1f_Wih, l1b_Wih,
                          ehW, emW, lmW, lhW,
                          l0f_b, l0b_b, l1f_b, l1b_b, ehb, emb, lmb, lhb,
                          l0f_Whh, l0b_Whh, l1f_Whh, l1b_Whh);
    k_embed<<<4096, 128>>>(wid, uid, wl, tl);

    cudaFuncSetAttribute(k_scan, cudaFuncAttributeMaxDynamicSharedMemorySize, SCAN_SMEM);

    k_gemm<<<dim3(8, 64, 2), 256>>>(WORDS, WIH0, B0, XG0F, 500, 128,
                                    512 * 128, 512, 2048000LL);
    k_scan<<<64, 512, SCAN_SMEM>>>(XG0F, XG0B, wpk, wpk + 32256, H0);
    k_gemm<<<dim3(8, 64, 2), 256>>>(H0, WIH1, B1, XG1F, 500, 256,
                                    512 * 256, 512, 2048000LL);
    k_scan<<<64, 512, SCAN_SMEM>>>(XG1F, XG1B, wpk + 2 * 32256, wpk + 3 * 32256, WE1);
    k_gemm<<<dim3(7, 64, 1), 256>>>(WE1, SW, SB, SCOR, 400, 256, 0, 0, 0LL);

    cudaFuncSetAttribute(k_arc, cudaFuncAttributeMaxDynamicSharedMemorySize, 60000);
    k_arc<<<dim3(8, 32), 256, 58656>>>(esW, esb, out + 8192, out);
    k_rel<<<4096, 64>>>(lsW, lsb, out + 532480, out + 4096);
}

// round 15
// speedup vs baseline: 1.1064x; 1.0289x over previous
#include <cuda_runtime.h>
#include <cstdint>
#include <math.h>

typedef unsigned long long ULL;

// ---------------- scratch offsets (floats) ----------------
#define OFF_WORDS 0ull                               // 4096*128
#define OFF_XG0F (OFF_WORDS + 524288ull)             // 4096*500
#define OFF_XG0B (OFF_XG0F + 2048000ull)
#define OFF_XG1F (OFF_XG0B + 2048000ull)
#define OFF_XG1B (OFF_XG1F + 2048000ull)
#define OFF_H0   (OFF_XG1B + 2048000ull)             // 4096*256
#define OFF_WE1  (OFF_H0   + 1048576ull)             // 4096*256
#define OFF_SCOR (OFF_WE1  + 1048576ull)             // 4096*400
#define OFF_WIH0 (OFF_SCOR + 1638400ull)             // 2*512*128
#define OFF_WIH1 (OFF_WIH0 + 131072ull)              // 2*512*256
#define OFF_SW   (OFF_WIH1 + 262144ull)              // 448*256
#define OFF_B0   (OFF_SW   + 114688ull)              // 2*512
#define OFF_B1   (OFF_B0   + 1024ull)                // 2*512
#define OFF_SB   (OFF_B1   + 1024ull)                // 448
#define SCR_TOT  (OFF_SB   + 448ull)

__device__ float g_scr[SCR_TOT];
__device__ int   g_tree[4096];
__device__ int   g_gidx[4096];
__device__ ULL   g_wpk[4 * 63 * 512];   // packed Whh pair image [ld][63][512]

// ---------------- f32x2 helpers ----------------
__device__ __forceinline__ ULL pk2(float x, float y) {
    ULL r; asm("mov.b64 %0,{%1,%2};" : "=l"(r) : "f"(x), "f"(y)); return r;
}
__device__ __forceinline__ float2 upk2(ULL v) {
    float2 r; asm("mov.b64 {%0,%1},%2;" : "=f"(r.x), "=f"(r.y) : "l"(v)); return r;
}
__device__ __forceinline__ void fma2(ULL& c, ULL a, ULL b) {
    asm("fma.rn.f32x2 %0,%1,%2,%0;" : "+l"(c) : "l"(a), "l"(b));
}
__device__ __forceinline__ float sig_f(float x) {
    x = fminf(15.f, fmaxf(-15.f, x));
    float e; asm("ex2.approx.f32 %0,%1;" : "=f"(e) : "f"(-1.4426950408889634f * x));
    float r; asm("rcp.approx.f32 %0,%1;" : "=f"(r) : "f"(1.f + e));
    return r;
}
__device__ __forceinline__ float tanh_f(float x) {
    x = fminf(15.f, fmaxf(-15.f, x));
    float e; asm("ex2.approx.f32 %0,%1;" : "=f"(e) : "f"(2.885390081777927f * x));
    float r; asm("rcp.approx.f32 %0,%1;" : "=f"(r) : "f"(e + 1.f));
    return (e - 1.f) * r;
}
__device__ __forceinline__ float ex2c(float a) {     // 2^clamp(a,±45)
    a = fminf(45.f, fmaxf(-45.f, a));
    float e; asm("ex2.approx.f32 %0,%1;" : "=f"(e) : "f"(a));
    return e;
}
__device__ __forceinline__ uint32_t sa(const void* p) {
    return (uint32_t)__cvta_generic_to_shared(p);
}

// ---------------- prep: pack/pad weights, biases, tree/gidx, Whh image ----------------
__global__ void k_prep(const int* __restrict__ tarc,
                       const float* __restrict__ l0fW, const float* __restrict__ l0bW,
                       const float* __restrict__ l1fW, const float* __restrict__ l1bW,
                       const float* __restrict__ ehW, const float* __restrict__ emW,
                       const float* __restrict__ lmW, const float* __restrict__ lhW,
                       const float* __restrict__ l0fb, const float* __restrict__ l0bb,
                       const float* __restrict__ l1fb, const float* __restrict__ l1bb,
                       const float* __restrict__ ehb, const float* __restrict__ emb,
                       const float* __restrict__ lmb, const float* __restrict__ lhb,
                       const float* __restrict__ whl0f, const float* __restrict__ whl0b,
                       const float* __restrict__ whl1f, const float* __restrict__ whl1b) {
    int idx = blockIdx.x * 256 + threadIdx.x;
    const int E0 = 131072, E1 = E0 + 262144, E2 = E1 + 114688, E3 = E2 + 1024,
              E4 = E3 + 1024, E5 = E4 + 448, E6 = E5 + 4096, E7 = E6 + 24576,
              E8 = E7 + 24576, E9 = E8 + 129024;
    if (idx < E0) {                       // WIH0 [2][512][128]
        int z = idx >> 16, r = idx & 65535, n = r >> 7, k = r & 127;
        const float* s = z ? l0bW : l0fW;
        g_scr[OFF_WIH0 + idx] = (n < 500 && k < 125) ? s[n * 125 + k] : 0.f;
    } else if (idx < E1) {                // WIH1 [2][512][256]
        int i = idx - E0, z = i >> 17, r = i & 131071, n = r >> 8, k = r & 255;
        const float* s = z ? l1bW : l1fW;
        g_scr[OFF_WIH1 + i] = (n < 500 && k < 250) ? s[n * 250 + k] : 0.f;
    } else if (idx < E2) {                // SW [448][256]
        int i = idx - E1, n = i >> 8, k = i & 255;
        float v = 0.f;
        if (k < 250 && n < 400) {
            int sel = n / 100, nn = n - sel * 100;
            const float* s = sel == 0 ? ehW : sel == 1 ? emW : sel == 2 ? lmW : lhW;
            v = s[nn * 250 + k];
        }
        g_scr[OFF_SW + i] = v;
    } else if (idx < E3) {                // B0 [2][512]
        int i = idx - E2, z = i >> 9, n = i & 511;
        g_scr[OFF_B0 + i] = (n < 500) ? (z ? l0bb[n] : l0fb[n]) : 0.f;
    } else if (idx < E4) {                // B1 [2][512]
        int i = idx - E3, z = i >> 9, n = i & 511;
        g_scr[OFF_B1 + i] = (n < 500) ? (z ? l1bb[n] : l1fb[n]) : 0.f;
    } else if (idx < E5) {                // SB [448]
        int n = idx - E4;
        float v = 0.f;
        if (n < 400) {
            int sel = n / 100, nn = n - sel * 100;
            v = sel == 0 ? ehb[nn] : sel == 1 ? emb[nn] : sel == 2 ? lmb[nn] : lhb[nn];
        }
        g_scr[OFF_SB + n] = v;
    } else if (idx < E6) {                // tree + gidx
        int m = idx - E5;
        int v = ((m & 127) == 0) ? 0 : tarc[m];
        g_tree[m] = v;
        g_gidx[m] = (m >> 7) * 128 + v;
    } else if (idx < E7) {                // H0 pad cols 250..255
        int i = idx - E6, m = i / 6, c = i - m * 6;
        g_scr[OFF_H0 + (size_t)m * 256 + 250 + c] = 0.f;
    } else if (idx < E8) {                // WE1 pad cols
        int i = idx - E7, m = i / 6, c = i - m * 6;
        g_scr[OFF_WE1 + (size_t)m * 256 + 250 + c] = 0.f;
    } else if (idx < E9) {                // g_wpk [4][63][512]
        int i = idx - E8;
        int ld = i / 32256, rem = i - ld * 32256;
        int k = rem >> 9, r = rem & 511;
        const float* s = ld == 0 ? whl0f : ld == 1 ? whl0b : ld == 2 ? whl1f : whl1b;
        float w0 = 0.f, w1 = 0.f;
        if (r < 500) {
            int c0 = 2 * k, c1 = 2 * k + 1;
            if (c0 < 125) w0 = s[r * 125 + c0];
            if (c1 < 125) w1 = s[r * 125 + c1];
        }
        g_wpk[i] = pk2(w0, w1);
    }
}

// ---------------- embedding gather: words[4096,128] (padded) ----------------
__global__ void k_embed(const int* __restrict__ wid, const int* __restrict__ uid,
                        const float* __restrict__ wl, const float* __restrict__ tl) {
    int m = blockIdx.x, t = threadIdx.x;
    float* w = g_scr + OFF_WORDS + (size_t)m * 128;
    float v = 0.f;
    if (t < 100)      v = wl[(size_t)wid[m] * 100 + t];
    else if (t < 125) v = tl[(size_t)uid[m] * 25 + (t - 100)];
    w[t] = v;
}

// ---------------- GEMM: BM=128 BN=64 BK=32, 8x4 microtile, f32x2 ----------------
__global__ void __launch_bounds__(256) k_gemm(const float* __restrict__ A,
                                              const float* __restrict__ Wp,
                                              const float* __restrict__ Bp,
                                              float* __restrict__ C,
                                              int N, int K, int ldWz, int bstride,
                                              long long zsC) {
    __shared__ __align__(16) float As[32][132];   // 528B rows, 16B-aligned
    __shared__ __align__(16) float Ws[32][68];
    int z = blockIdx.z;
    const float* Wz = Wp + (size_t)z * ldWz;
    const float* bz = Bp + (size_t)z * bstride;
    float* Cz = C + (size_t)z * zsC;
    int t = threadIdx.x, tx = t & 15, ty = t >> 4;
    int m0 = blockIdx.y * 128, n0 = blockIdx.x * 64;
    int mf = t >> 3, kg = t & 7;

    ULL acc[4][4];
#pragma unroll
    for (int i = 0; i < 4; i++)
#pragma unroll
        for (int j = 0; j < 4; j++) acc[i][j] = 0ull;

    uint32_t aAddr = sa(&As[0][ty * 8]);

    for (int k0 = 0; k0 < K; k0 += 32) {
        // A tile 128x32: 4 rows per thread
#pragma unroll
        for (int i = 0; i < 4; i++) {
            int row = mf + 32 * i;
            float4 av = *(const float4*)(A + (size_t)(m0 + row) * K + k0 + kg * 4);
            As[kg * 4 + 0][row] = av.x; As[kg * 4 + 1][row] = av.y;
            As[kg * 4 + 2][row] = av.z; As[kg * 4 + 3][row] = av.w;
        }
        // W tile 64x32: 2 rows per thread
        {
            float4 wv1 = *(const float4*)(Wz + (size_t)(n0 + mf) * K + k0 + kg * 4);
            float4 wv2 = *(const float4*)(Wz + (size_t)(n0 + mf + 32) * K + k0 + kg * 4);
            Ws[kg * 4 + 0][mf] = wv1.x; Ws[kg * 4 + 1][mf] = wv1.y;
            Ws[kg * 4 + 2][mf] = wv1.z; Ws[kg * 4 + 3][mf] = wv1.w;
            Ws[kg * 4 + 0][mf + 32] = wv2.x; Ws[kg * 4 + 1][mf + 32] = wv2.y;
            Ws[kg * 4 + 2][mf + 32] = wv2.z; Ws[kg * 4 + 3][mf + 32] = wv2.w;
        }
        __syncthreads();
#pragma unroll
        for (int k = 0; k < 32; k++) {
            ULL a0, a1, a2, a3;
            asm volatile("ld.shared.v2.u64 {%0,%1},[%2];"
                         : "=l"(a0), "=l"(a1) : "r"(aAddr + k * 528));
            asm volatile("ld.shared.v2.u64 {%0,%1},[%2];"
                         : "=l"(a2), "=l"(a3) : "r"(aAddr + k * 528 + 16));
            float4 wv = *(const float4*)&Ws[k][tx * 4];
            ULL w0 = pk2(wv.x, wv.x), w1 = pk2(wv.y, wv.y);
            ULL w2 = pk2(wv.z, wv.z), w3 = pk2(wv.w, wv.w);
            fma2(acc[0][0], a0, w0); fma2(acc[0][1], a0, w1);
            fma2(acc[0][2], a0, w2); fma2(acc[0][3], a0, w3);
            fma2(acc[1][0], a1, w0); fma2(acc[1][1], a1, w1);
            fma2(acc[1][2], a1, w2); fma2(acc[1][3], a1, w3);
            fma2(acc[2][0], a2, w0); fma2(acc[2][1], a2, w1);
            fma2(acc[2][2], a2, w2); fma2(acc[2][3], a2, w3);
            fma2(acc[3][0], a3, w0); fma2(acc[3][1], a3, w1);
            fma2(acc[3][2], a3, w2); fma2(acc[3][3], a3, w3);
        }
        __syncthreads();
    }
    int n = n0 + tx * 4;
    float b0 = (n     < N) ? bz[n]     : 0.f;
    float b1 = (n + 1 < N) ? bz[n + 1] : 0.f;
    float b2 = (n + 2 < N) ? bz[n + 2] : 0.f;
    float b3 = (n + 3 < N) ? bz[n + 3] : 0.f;
#pragma unroll
    for (int i = 0; i < 4; i++) {
        float2 p0 = upk2(acc[i][0]), p1 = upk2(acc[i][1]);
        float2 p2 = upk2(acc[i][2]), p3 = upk2(acc[i][3]);
#pragma unroll
        for (int rr = 0; rr < 2; rr++) {
            int m = m0 + ty * 8 + 2 * i + rr;
            float4 v = rr ? make_float4(p0.y + b0, p1.y + b1, p2.y + b2, p3.y + b3)
                          : make_float4(p0.x + b0, p1.x + b1, p2.x + b2, p3.x + b3);
            if (n + 3 < N) {
                *(float4*)(Cz + (size_t)m * N + n) = v;
            } else {
                float vv[4] = {v.x, v.y, v.z, v.w};
                for (int jj = 0; jj < 4; jj++)
                    if (n + jj < N) Cz[(size_t)m * N + n + jj] = vv[jj];
            }
        }
    }
}

// ---------------- LSTM scan (R11/R14 best): ONE CTA per (b,dir) ----------------
#define SPAIR 19
#define SCAN_SMEM (SPAIR * 512 * 8 + 128 * 4 + 512 * 4)
__global__ void __launch_bounds__(512, 1)
k_scan(const float* __restrict__ xgf, const float* __restrict__ xgb,
       const ULL* __restrict__ wpkF, const ULL* __restrict__ wpkB,
       float* __restrict__ hout) {
    extern __shared__ __align__(16) char dyn[];
    ULL*   wsp  = (ULL*)dyn;                          // [SPAIR][512]
    float* h    = (float*)(dyn + SPAIR * 512 * 8);    // [128]
    float* gacc = h + 128;                            // [512]
    int bid = blockIdx.x;
    int b = bid & 31, dir = bid >> 5;
    const float* xg = dir ? xgb : xgf;
    const ULL* wpk  = dir ? wpkB : wpkF;
    int t = threadIdx.x;
    bool act = t < 500;
    int r = act ? t : 0;

    ULL wreg[44];
#pragma unroll
    for (int k = 0; k < 44; k++)
        wreg[k] = wpk[k * 512 + t];
#pragma unroll
    for (int k = 0; k < SPAIR; k++)
        wsp[k * 512 + t] = wpk[(44 + k) * 512 + t];
    if (t < 128) h[t] = 0.f;
    __syncthreads();

    uint32_t hA = sa(h);
    uint32_t wA = sa(wsp) + (uint32_t)t * 8;
    float c = 0.f;
    const size_t brow = (size_t)b * 128;
    float xvc = act ? xg[(brow + (dir ? 127 : 0)) * 500 + r] : 0.f;
    float xvn = act ? xg[(brow + (dir ? 126 : 1)) * 500 + r] : 0.f;
    bool istanh = (t >= 250 && t < 375);

    for (int s = 0; s < 128; s++) {
        int tt = dir ? (127 - s) : s;
        ULL a0 = 0ull, a1 = 0ull, a2 = 0ull, a3 = 0ull;
#pragma unroll
        for (int i = 0; i < 22; i++) {
            ULL h01, h23;
            asm volatile("ld.shared.v2.u64 {%0,%1},[%2];"
                         : "=l"(h01), "=l"(h23) : "r"(hA + i * 16));
            if (i & 1) { fma2(a2, h01, wreg[2 * i]); fma2(a3, h23, wreg[2 * i + 1]); }
            else       { fma2(a0, h01, wreg[2 * i]); fma2(a1, h23, wreg[2 * i + 1]); }
        }
#pragma unroll
        for (int i = 0; i < 9; i++) {
            ULL h01, h23, w01, w23;
            asm volatile("ld.shared.v2.u64 {%0,%1},[%2];"
                         : "=l"(h01), "=l"(h23) : "r"(hA + 352 + i * 16));
            asm volatile("ld.shared.u64 %0,[%1];"
                         : "=l"(w01) : "r"(wA + (2 * i) * 4096));
            asm volatile("ld.shared.u64 %0,[%1];"
                         : "=l"(w23) : "r"(wA + (2 * i + 1) * 4096));
            if (i & 1) { fma2(a2, h01, w01); fma2(a3, h23, w23); }
            else       { fma2(a0, h01, w01); fma2(a1, h23, w23); }
        }
        {
            ULL h01, w01;
            asm volatile("ld.shared.u64 %0,[%1];" : "=l"(h01) : "r"(hA + 496));
            asm volatile("ld.shared.u64 %0,[%1];" : "=l"(w01) : "r"(wA + 18 * 4096));
            fma2(a0, h01, w01);
        }
        float2 f0 = upk2(a0), f1 = upk2(a1), f2 = upk2(a2), f3 = upk2(a3);
        float g = ((f0.x + f0.y) + (f1.x + f1.y)) + ((f2.x + f2.y) + (f3.x + f3.y)) + xvc;
        gacc[t] = istanh ? tanh_f(g) : sig_f(g);
        xvc = xvn;
        if (s + 2 < 128) {
            int tn = dir ? (125 - s) : (s + 2);
            xvn = act ? xg[(brow + tn) * 500 + r] : 0.f;
        }
        __syncthreads();
        if (t < 125) {
            float si = gacc[t], sf = gacc[125 + t], tg = gacc[250 + t], so = gacc[375 + t];
            c = sf * c + si * tg;
            float hh = so * tanh_f(c);
            h[t] = hh;
            hout[(brow + tt) * 256 + dir * 125 + t] = hh;
        }
        __syncthreads();
    }
}

// ---------------- biaffine arc scores: precomputed exponentials, 1 MUFU/elem ----------------
// tanh(a+b) = 1 - 2/(Ea*Eb + 1), E = 2^(2*log2e*x) clamped to 2^±45.
__global__ void __launch_bounds__(256) k_arc(const float* __restrict__ esW,
                                             const float* __restrict__ esb,
                                             float* __restrict__ arc_out,
                                             float* __restrict__ parsed_out) {
    extern __shared__ float sm[];
    float* ejs   = sm;                 // 128*101  E_j
    float* eis   = sm + 128 * 101;     // 16*101   E_i
    float* esw   = eis + 16 * 101;     // 100
    float* baseS = esw + 100;          // 1
    int*   treei = (int*)(baseS + 1);  // 16
    const float S2 = 2.885390081777927f; // 2*log2(e)
    int b = blockIdx.y, i0 = blockIdx.x * 16;
    int t = threadIdx.x;
    const float* wm = g_scr + OFF_SCOR + (size_t)b * 128 * 400 + 100;
    const float* wh = g_scr + OFF_SCOR + ((size_t)b * 128 + i0) * 400;
    for (int idx = t; idx < 12800; idx += 256) {
        int j = idx / 100, h = idx - j * 100;
        ejs[j * 101 + h] = ex2c(wm[(size_t)j * 400 + h] * S2);
    }
    for (int idx = t; idx < 1600; idx += 256) {
        int ii = idx / 100, h = idx - ii * 100;
        eis[ii * 101 + h] = ex2c(wh[(size_t)ii * 400 + h] * S2);
    }
    if (t < 100) esw[t] = -2.f * esW[t];
    if (t == 0) {
        float ssum = 0.f;
        for (int h = 0; h < 100; h++) ssum += esW[h];
        baseS[0] = ssum + esb[0] + 1.f;
    }
    if (t < 16) treei[t] = g_tree[b * 128 + i0 + t];
    __syncthreads();

    int ii = t >> 4, jl = t & 15;
    int i = i0 + ii;
    int tgt = treei[ii];
    float base = baseS[0];
    float best = -1e30f; int bj = 0;
    float* arow = arc_out + ((size_t)b * 128 + i) * 128;
    const float* Arow = eis + ii * 101;
    for (int jt = 0; jt < 8; jt++) {
        int j = jl + 16 * jt;
        const float* Brow = ejs + j * 101;
        float acc = 0.f;
#pragma unroll
        for (int h = 0; h < 100; h++) {
            float p = Arow[h] * Brow[h];
            float rr; asm("rcp.approx.f32 %0, %1;" : "=f"(rr) : "f"(p + 1.f));
            acc = fmaf(esw[h], rr, acc);
        }
        float sc = base + acc - ((j == tgt) ? 1.f : 0.f);
        arow[j] = sc;
        if (sc > best) { best = sc; bj = j; }
    }
    for (int off = 8; off; off >>= 1) {
        float ob = __shfl_xor_sync(0xffffffffu, best, off);
        int   oj = __shfl_xor_sync(0xffffffffu, bj, off);
        if (ob > best || (ob == best && oj < bj)) { best = ob; bj = oj; }
    }
    if (jl == 0) parsed_out[b * 128 + i] = (float)bj;
}

// ---------------- rel scores + argmax (head gather post-projection) ----------------
__global__ void k_rel(const float* __restrict__ lsW, const float* __restrict__ lsb,
                      float* __restrict__ rel_out, float* __restrict__ pred_out) {
    __shared__ float th[100];
    __shared__ float sc[50];
    int m = blockIdx.x, t = threadIdx.x;
    const float* rm = g_scr + OFF_SCOR + (size_t)m * 400 + 200;
    const float* rh = g_scr + OFF_SCOR + (size_t)g_gidx[m] * 400 + 300;
    for (int h = t; h < 100; h += 64) th[h] = tanhf(rm[h] + rh[h]);
    __syncthreads();
    if (t < 50) {
        float acc = lsb[t];
        const float* wr = lsW + t * 100;
#pragma unroll 10
        for (int h = 0; h < 100; h++) acc = fmaf(th[h], wr[h], acc);
        rel_out[(size_t)m * 50 + t] = acc;
        sc[t] = acc;
    }
    __syncthreads();
    if (t == 0) {
        float best = sc[0]; int bl = 0;
        for (int l = 1; l < 50; l++) if (sc[l] > best) { best = sc[l]; bl = l; }
        pred_out[m] = (float)bl;
    }
}

// ---------------- launch ----------------
extern "C" void kernel_launch(void* const* d_in, const int* in_sizes, int n_in,
                              void* d_out, int out_size) {
    const int* wid  = (const int*)d_in[0];
    const int* uid  = (const int*)d_in[1];
    const int* tarc = (const int*)d_in[2];
    const float* wl = (const float*)d_in[3];
    const float* tl = (const float*)d_in[4];
    const float* l0f_Wih = (const float*)d_in[5];
    const float* l0f_Whh = (const float*)d_in[6];
    const float* l0f_b   = (const float*)d_in[7];
    const float* l0b_Wih = (const float*)d_in[8];
    const float* l0b_Whh = (const float*)d_in[9];
    const float* l0b_b   = (const float*)d_in[10];
    const float* l1f_Wih = (const float*)d_in[11];
    const float* l1f_Whh = (const float*)d_in[12];
    const float* l1f_b   = (const float*)d_in[13];
    const float* l1b_Wih = (const float*)d_in[14];
    const float* l1b_Whh = (const float*)d_in[15];
    const float* l1b_b   = (const float*)d_in[16];
    const float* ehW = (const float*)d_in[17];
    const float* ehb = (const float*)d_in[18];
    const float* emW = (const float*)d_in[19];
    const float* emb = (const float*)d_in[20];
    const float* esW = (const float*)d_in[21];
    const float* esb = (const float*)d_in[22];
    const float* lhW = (const float*)d_in[23];
    const float* lhb = (const float*)d_in[24];
    const float* lmW = (const float*)d_in[25];
    const float* lmb = (const float*)d_in[26];
    const float* lsW = (const float*)d_in[27];
    const float* lsb = (const float*)d_in[28];
    float* out = (float*)d_out;

    float* scr = nullptr;
    cudaGetSymbolAddress((void**)&scr, g_scr);
    ULL* wpk = nullptr;
    cudaGetSymbolAddress((void**)&wpk, g_wpk);
    float* WORDS = scr + OFF_WORDS;
    float* XG0F = scr + OFF_XG0F;
    float* XG0B = scr + OFF_XG0B;
    float* XG1F = scr + OFF_XG1F;
    float* XG1B = scr + OFF_XG1B;
    float* H0   = scr + OFF_H0;
    float* WE1  = scr + OFF_WE1;
    float* SCOR = scr + OFF_SCOR;
    float* WIH0 = scr + OFF_WIH0;
    float* WIH1 = scr + OFF_WIH1;
    float* SW   = scr + OFF_SW;
    float* B0   = scr + OFF_B0;
    float* B1   = scr + OFF_B1;
    float* SB   = scr + OFF_SB;

    // 692672 total prep elements -> 2706 blocks of 256
    k_prep<<<2706, 256>>>(tarc, l0f_Wih, l0b_Wih, l1f_Wih, l1b_Wih,
                          ehW, emW, lmW, lhW,
                          l0f_b, l0b_b, l1f_b, l1b_b, ehb, emb, lmb, lhb,
                          l0f_Whh, l0b_Whh, l1f_Whh, l1b_Whh);
    k_embed<<<4096, 128>>>(wid, uid, wl, tl);

    cudaFuncSetAttribute(k_scan, cudaFuncAttributeMaxDynamicSharedMemorySize, SCAN_SMEM);

    k_gemm<<<dim3(8, 32, 2), 256>>>(WORDS, WIH0, B0, XG0F, 500, 128,
                                    512 * 128, 512, 2048000LL);
    k_scan<<<64, 512, SCAN_SMEM>>>(XG0F, XG0B, wpk, wpk + 32256, H0);
    k_gemm<<<dim3(8, 32, 2), 256>>>(H0, WIH1, B1, XG1F, 500, 256,
                                    512 * 256, 512, 2048000LL);
    k_scan<<<64, 512, SCAN_SMEM>>>(XG1F, XG1B, wpk + 2 * 32256, wpk + 3 * 32256, WE1);
    k_gemm<<<dim3(7, 32, 1), 256>>>(WE1, SW, SB, SCOR, 400, 256, 0, 0, 0LL);

    cudaFuncSetAttribute(k_arc, cudaFuncAttributeMaxDynamicSharedMemorySize, 60000);
    k_arc<<<dim3(8, 32), 256, 58656>>>(esW, esb, out + 8192, out);
    k_rel<<<4096, 64>>>(lsW, lsb, out + 532480, out + 4096);
}